// round 15
// baseline (speedup 1.0000x reference)
#include <cuda_runtime.h>
#include <cuda_bf16.h>
#include <math.h>
#include <stdint.h>

#define Bb   2
#define Lseq 1024
#define DM   768
#define DI   1536
#define NS   16
#define DTR  96
#define XDB  (DTR + 2*NS)   // 128
#define TT   (Bb*Lseq)      // 2048

#define IN_W  (2*DI*DM)
#define XP_W  (XDB*DI)
#define DT_W  (DI*DTR)
#define OUT_W (DM*2*DI)
#define WTOT  (2*IN_W + 2*XP_W + 2*DT_W + OUT_W)   // 7766016
#define NCVT  (WTOT/8/256)                          // 3792 blocks
#define OSPLIT 2
#define XSPLIT 4

// ---------------- fp32 scratch ----------------
__device__ float g_xdp[2*XSPLIT][TT*XDB];
__device__ float g_odp[OSPLIT][TT*DM];
__device__ float g_ycf[2][TT*DI];
// ---------------- bf16 scratch ----------------
__device__ __nv_bfloat16 g_un_bf[TT*DM];
__device__ __nv_bfloat16 g_xz_bf[2][TT*2*DI];
__device__ __nv_bfloat16 g_xc_bf[2][TT*DI];     // [t][d]  (xproj input)
__device__ __nv_bfloat16 g_xcT_bf[2][DI*TT];    // [d][t]  (scan input)
__device__ __nv_bfloat16 g_xd_bf[2][TT*XDB];    // [t][c]  (dt GEMM input)
__device__ __nv_bfloat16 g_xdT_bf[2][2*NS*TT];  // [c-96][t] (scan B/C)
__device__ __nv_bfloat16 g_dtT_bf[2][DI*TT];    // [d][t]  (scan dt)
__device__ __nv_bfloat16 g_ycat_bf[TT*2*DI];
__device__ __nv_bfloat16 g_inw_bf[2][IN_W];
__device__ __nv_bfloat16 g_xpw_bf[2][XP_W];
__device__ __nv_bfloat16 g_dtw_bf[2][DT_W];
__device__ __nv_bfloat16 g_outw_bf[OUT_W];

// ---------------- helpers ----------------
__device__ __forceinline__ void cp16(uint32_t dst_s, const void* src) {
    asm volatile("cp.async.ca.shared.global [%0], [%1], 16;\n" :: "r"(dst_s), "l"(src));
}
__device__ __forceinline__ void cp_commit() {
    asm volatile("cp.async.commit_group;\n");
}
template<int N> __device__ __forceinline__ void cp_wait() {
    asm volatile("cp.async.wait_group %0;\n" :: "n"(N));
}
__device__ __forceinline__ void ldsm4(uint32_t& r0, uint32_t& r1,
                                      uint32_t& r2, uint32_t& r3, uint32_t a) {
    asm volatile("ldmatrix.sync.aligned.m8n8.x4.shared.b16 {%0,%1,%2,%3}, [%4];\n"
        : "=r"(r0), "=r"(r1), "=r"(r2), "=r"(r3) : "r"(a));
}
__device__ __forceinline__ void mma_bf16(
    float& c0, float& c1, float& c2, float& c3,
    uint32_t a0, uint32_t a1, uint32_t a2, uint32_t a3,
    uint32_t b0, uint32_t b1)
{
    asm volatile(
        "mma.sync.aligned.m16n8k16.row.col.f32.bf16.bf16.f32 "
        "{%0,%1,%2,%3}, {%4,%5,%6,%7}, {%8,%9}, {%0,%1,%2,%3};\n"
        : "+f"(c0), "+f"(c1), "+f"(c2), "+f"(c3)
        : "r"(a0), "r"(a1), "r"(a2), "r"(a3), "r"(b0), "r"(b1));
}
__device__ __forceinline__ uint32_t pk2(float a, float b) {
    __nv_bfloat162 h = __float22bfloat162_rn(make_float2(a, b));
    return *reinterpret_cast<uint32_t*>(&h);
}
__device__ __forceinline__ void ld4bf(const __nv_bfloat16* p, float* o) {
    uint2 r = *(const uint2*)p;
    __nv_bfloat162 lo = *reinterpret_cast<__nv_bfloat162*>(&r.x);
    __nv_bfloat162 hi = *reinterpret_cast<__nv_bfloat162*>(&r.y);
    float2 f0 = __bfloat1622float2(lo);
    float2 f1 = __bfloat1622float2(hi);
    o[0] = f0.x; o[1] = f0.y; o[2] = f1.x; o[3] = f1.y;
}
// 8 consecutive bf16 (16B aligned) -> 8 floats
__device__ __forceinline__ void ld8bf(const __nv_bfloat16* p, float* o) {
    uint4 r = *(const uint4*)p;
    __nv_bfloat162 h0 = *reinterpret_cast<__nv_bfloat162*>(&r.x);
    __nv_bfloat162 h1 = *reinterpret_cast<__nv_bfloat162*>(&r.y);
    __nv_bfloat162 h2 = *reinterpret_cast<__nv_bfloat162*>(&r.z);
    __nv_bfloat162 h3 = *reinterpret_cast<__nv_bfloat162*>(&r.w);
    float2 f0 = __bfloat1622float2(h0);
    float2 f1 = __bfloat1622float2(h1);
    float2 f2 = __bfloat1622float2(h2);
    float2 f3 = __bfloat1622float2(h3);
    o[0]=f0.x; o[1]=f0.y; o[2]=f1.x; o[3]=f1.y;
    o[4]=f2.x; o[5]=f2.y; o[6]=f3.x; o[7]=f3.y;
}

// ---------------- prep: weight cvt + layernorm ----------------
__global__ __launch_bounds__(256) void prep_kernel(
    const float* __restrict__ u, const float* __restrict__ nw,
    const float* __restrict__ nb,
    const float* __restrict__ fw, const float* __restrict__ bw,
    const float* __restrict__ fx, const float* __restrict__ bx,
    const float* __restrict__ fd, const float* __restrict__ bd,
    const float* __restrict__ ow)
{
    if (blockIdx.x < NCVT) {
        long long i = ((long long)blockIdx.x * 256 + threadIdx.x) * 8;
        const float* s; __nv_bfloat16* dst;
        if (i < IN_W)                 { s = fw + i; dst = &g_inw_bf[0][i]; }
        else if ((i -= IN_W) < IN_W)  { s = bw + i; dst = &g_inw_bf[1][i]; }
        else if ((i -= IN_W) < XP_W)  { s = fx + i; dst = &g_xpw_bf[0][i]; }
        else if ((i -= XP_W) < XP_W)  { s = bx + i; dst = &g_xpw_bf[1][i]; }
        else if ((i -= XP_W) < DT_W)  { s = fd + i; dst = &g_dtw_bf[0][i]; }
        else if ((i -= DT_W) < DT_W)  { s = bd + i; dst = &g_dtw_bf[1][i]; }
        else if ((i -= DT_W) < OUT_W) { s = ow + i; dst = &g_outw_bf[i]; }
        else return;
        float4 lo = *(const float4*)s;
        float4 hi = *(const float4*)(s + 4);
        uint4 o;
        o.x = pk2(lo.x, lo.y); o.y = pk2(lo.z, lo.w);
        o.z = pk2(hi.x, hi.y); o.w = pk2(hi.z, hi.w);
        *(uint4*)dst = o;
        return;
    }
    int t = blockIdx.x - NCVT;
    const float* row = u + (size_t)t * DM;
    float v[3];
    float s = 0.f, s2 = 0.f;
#pragma unroll
    for (int i = 0; i < 3; i++) {
        v[i] = row[threadIdx.x + i*256];
        s  += v[i];
        s2 += v[i]*v[i];
    }
#pragma unroll
    for (int o = 16; o; o >>= 1) {
        s  += __shfl_xor_sync(0xffffffffu, s,  o);
        s2 += __shfl_xor_sync(0xffffffffu, s2, o);
    }
    __shared__ float ss[8], ss2[8];
    int wid = threadIdx.x >> 5, ln = threadIdx.x & 31;
    if (ln == 0) { ss[wid] = s; ss2[wid] = s2; }
    __syncthreads();
    float ts = 0.f, ts2 = 0.f;
#pragma unroll
    for (int i = 0; i < 8; i++) { ts += ss[i]; ts2 += ss2[i]; }
    float mu  = ts * (1.f/DM);
    float var = ts2 * (1.f/DM) - mu*mu;
    float rs  = rsqrtf(var + 1e-5f);
#pragma unroll
    for (int i = 0; i < 3; i++) {
        int c = threadIdx.x + i*256;
        g_un_bf[(size_t)t*DM + c] = __float2bfloat16((v[i]-mu)*rs*nw[c] + nb[c]);
    }
}

// fragment-load macro (double-buffered) for gemm_big
#define LDFRAG_BIG(B, KK) do {                                                \
    _Pragma("unroll")                                                         \
    for (int ii = 0; ii < 4; ii++) {                                          \
        int row = wm*64 + ii*16 + arow;                                       \
        int pos = (2*(KK) + ach) ^ (row & 7);                                 \
        ldsm4(ar[B][ii][0], ar[B][ii][1], ar[B][ii][2], ar[B][ii][3],         \
              base + row*128 + pos*16);                                       \
    }                                                                         \
    _Pragma("unroll")                                                         \
    for (int j2 = 0; j2 < 4; j2++) {                                          \
        int row = wn*64 + j2*16 + brow;                                       \
        int pos = (2*(KK) + bch) ^ (row & 7);                                 \
        ldsm4(brr[B][2*j2][0], brr[B][2*j2][1],                               \
              brr[B][2*j2+1][0], brr[B][2*j2+1][1],                           \
              base + 16384 + row*128 + pos*16);                               \
    }                                                                         \
} while (0)

// ======== gemm_big: 128x128 CTA tile, 4 warps (64x64 each), k64 slabs ========
// MODE 0: bf16 out (z = branch).  MODE 3: split-K fp32 partials (z = k-chunk).
template<int MODE>
__global__ void __launch_bounds__(128) gemm_big(
    const __nv_bfloat16* __restrict__ A0, const __nv_bfloat16* __restrict__ A1, int lda,
    const __nv_bfloat16* __restrict__ W0, const __nv_bfloat16* __restrict__ W1, int ldw,
    float* __restrict__ C0, int ldc,
    __nv_bfloat16* __restrict__ Cb0, __nv_bfloat16* __restrict__ Cb1,
    int K)
{
    extern __shared__ char smem[];
    uint32_t sb = (uint32_t)__cvta_generic_to_shared(smem);

    const __nv_bfloat16* A;
    const __nv_bfloat16* W;
    float* C = nullptr;
    __nv_bfloat16* Cb = nullptr;
    if (MODE == 3) {
        A = A0 + (size_t)blockIdx.z * K;
        W = W0 + (size_t)blockIdx.z * K;
        C = C0 + (size_t)blockIdx.z * ((size_t)TT * DM);
    } else {
        A  = blockIdx.z ? A1 : A0;
        W  = blockIdx.z ? W1 : W0;
        Cb = blockIdx.z ? Cb1 : Cb0;
    }

    int tid  = threadIdx.x;
    int lane = tid & 31;
    int w    = tid >> 5;
    int wm   = w >> 1;
    int wn   = w & 1;
    int bm   = blockIdx.y * 128;
    int bn   = blockIdx.x * 128;

    int ch = tid & 7;
    int rb = tid >> 3;
    const __nv_bfloat16* ap = A + (size_t)(bm + rb) * lda + ch * 8;
    const __nv_bfloat16* wp = W + (size_t)(bn + rb) * ldw + ch * 8;
    uint32_t ao = (uint32_t)(rb * 128 + ((ch ^ (rb & 7)) * 16));
    uint32_t bo = 16384u + ao;

    int nk = K / 64;
#pragma unroll
    for (int p = 0; p < 2; p++) {
#pragma unroll
        for (int v = 0; v < 8; v++) {
            cp16(sb + p*32768 + ao + v*2048, ap + (size_t)v*16*lda + p*64);
            cp16(sb + p*32768 + bo + v*2048, wp + (size_t)v*16*ldw + p*64);
        }
        cp_commit();
    }

    float acc[4][8][4] = {};
    int arow = lane & 15;
    int ach  = lane >> 4;
    int brow = ((lane >> 4) << 3) + (lane & 7);
    int bch  = (lane >> 3) & 1;
    int r0   = lane >> 2;
    int c0   = lane & 3;

    uint32_t ar[2][4][4];
    uint32_t brr[2][8][2];

    for (int i = 0; i < nk; i++) {
        int st = i % 3;
        cp_wait<1>();
        __syncthreads();
        {
            int s2 = (i + 2) % 3;
            if (i + 2 < nk) {
#pragma unroll
                for (int v = 0; v < 8; v++) {
                    cp16(sb + s2*32768 + ao + v*2048, ap + (size_t)v*16*lda + (i+2)*64);
                    cp16(sb + s2*32768 + bo + v*2048, wp + (size_t)v*16*ldw + (i+2)*64);
                }
            }
            cp_commit();
        }
        uint32_t base = sb + st*32768;
        LDFRAG_BIG(0, 0);
#pragma unroll
        for (int kk = 0; kk < 4; kk++) {
            int cur = kk & 1;
            if (kk == 0) LDFRAG_BIG(1, 1);
            else if (kk == 1) LDFRAG_BIG(0, 2);
            else if (kk == 2) LDFRAG_BIG(1, 3);
#pragma unroll
            for (int ii = 0; ii < 4; ii++)
#pragma unroll
                for (int j = 0; j < 8; j++)
                    mma_bf16(acc[ii][j][0], acc[ii][j][1],
                             acc[ii][j][2], acc[ii][j][3],
                             ar[cur][ii][0], ar[cur][ii][1],
                             ar[cur][ii][2], ar[cur][ii][3],
                             brr[cur][j][0], brr[cur][j][1]);
        }
    }

#pragma unroll
    for (int ii = 0; ii < 4; ii++) {
        int m0 = bm + wm*64 + ii*16 + r0;
#pragma unroll
        for (int j = 0; j < 8; j++) {
            int n0 = bn + wn*64 + j*8 + c0*2;
            if (MODE == 3) {
                *(float2*)&C[(size_t)m0 * ldc + n0] =
                    make_float2(acc[ii][j][0], acc[ii][j][1]);
                *(float2*)&C[(size_t)(m0+8) * ldc + n0] =
                    make_float2(acc[ii][j][2], acc[ii][j][3]);
            } else {
                *(uint32_t*)&Cb[(size_t)m0 * ldc + n0] =
                    pk2(acc[ii][j][0], acc[ii][j][1]);
                *(uint32_t*)&Cb[(size_t)(m0+8) * ldc + n0] =
                    pk2(acc[ii][j][2], acc[ii][j][3]);
            }
        }
    }
}

// ---------------- out-proj reduce ----------------
__global__ __launch_bounds__(256) void reduce_out(const float* __restrict__ u,
                                                  float* __restrict__ out)
{
    int i4 = (blockIdx.x * 256 + threadIdx.x) * 4;
    if (i4 >= TT*DM) return;
    float4 s = *(const float4*)&u[i4];
#pragma unroll
    for (int p = 0; p < OSPLIT; p++) {
        float4 a = *(const float4*)&g_odp[p][i4];
        s.x += a.x; s.y += a.y; s.z += a.z; s.w += a.w;
    }
    *(float4*)&out[i4] = s;
}

// frag loads for 32x64-warp-tile kernels (xp, dt)
#define LDFRAG_SM(B, KK) do {                                                 \
    _Pragma("unroll")                                                         \
    for (int ii = 0; ii < 2; ii++) {                                          \
        int row = wm*32 + ii*16 + arow;                                       \
        int pos = (2*(KK) + ach) ^ ((row >> 1) & 3);                          \
        ldsm4(ar[B][ii][0], ar[B][ii][1], ar[B][ii][2], ar[B][ii][3],         \
              stw + (row*16 + pos*4)*4);                                      \
    }                                                                         \
    _Pragma("unroll")                                                         \
    for (int j2 = 0; j2 < 4; j2++) {                                          \
        int row = wn*64 + j2*16 + brow;                                       \
        int pos = (2*(KK) + bch) ^ ((row >> 1) & 3);                          \
        ldsm4(brr[B][2*j2][0], brr[B][2*j2][1],                               \
              brr[B][2*j2+1][0], brr[B][2*j2+1][1],                           \
              stw + (BMv*16 + row*16 + pos*4)*4);                             \
    }                                                                         \
} while (0)

// ======== gemm_xp: xproj split-K x4.  BM=64, BN=128, 4 warps (32x64), K=384 ========
__global__ void __launch_bounds__(128) gemm_xp(
    const __nv_bfloat16* __restrict__ Ab0, const __nv_bfloat16* __restrict__ Ab1,
    const __nv_bfloat16* __restrict__ Wb0, const __nv_bfloat16* __restrict__ Wb1,
    float* __restrict__ Cp)
{
    constexpr int BMv = 64, THREADS = 128;
    constexpr int SWORDS = (BMv + 128) * 16;
    constexpr int LPT = (BMv + 128) * 4 / THREADS;  // 6
    constexpr int KPART = DI / XSPLIT;              // 384

    extern __shared__ uint32_t sm[];
    uint32_t smem_base = (uint32_t)__cvta_generic_to_shared(sm);

    int z  = blockIdx.z;
    int br = z >> 2;
    int kp = z & 3;
    const __nv_bfloat16* A = (br ? Ab1 : Ab0) + kp * KPART;
    const __nv_bfloat16* W = (br ? Wb1 : Wb0) + kp * KPART;
    float* C = Cp + (size_t)z * (TT*XDB);

    int tid  = threadIdx.x;
    int lane = tid & 31;
    int w    = tid >> 5;
    int wm   = w >> 1;
    int wn   = w & 1;
    int bm   = blockIdx.y * BMv;
    int r0   = lane >> 2;
    int c0   = lane & 3;

    const __nv_bfloat16* lsrc[LPT];
    uint32_t ldst[LPT];
#pragma unroll
    for (int u = 0; u < LPT; u++) {
        int i   = tid + u * THREADS;
        int row = i >> 2;
        int x   = i & 3;
        if (row < BMv) {
            lsrc[u] = A + (size_t)(bm + row) * DI + x * 8;
            ldst[u] = row * 16 + (x ^ ((row >> 1) & 3)) * 4;
        } else {
            int r = row - BMv;
            lsrc[u] = W + (size_t)r * DI + x * 8;
            ldst[u] = BMv * 16 + r * 16 + (x ^ ((r >> 1) & 3)) * 4;
        }
    }

    constexpr int nk = KPART / 32;   // 12
#pragma unroll
    for (int p = 0; p < 3; p++) {
#pragma unroll
        for (int u = 0; u < LPT; u++)
            cp16(smem_base + (p*SWORDS + ldst[u])*4, lsrc[u] + p*32);
        cp_commit();
    }

    float acc[2][8][4] = {};
    int arow = lane & 15;
    int ach  = lane >> 4;
    int brow = ((lane >> 4) << 3) + (lane & 7);
    int bch  = (lane >> 3) & 1;

    uint32_t ar[2][2][4];
    uint32_t brr[2][8][2];

    for (int i = 0; i < nk; i++) {
        int st = i & 3;
        int rem = nk - 1 - i;
        if (rem >= 2)      cp_wait<2>();
        else if (rem == 1) cp_wait<1>();
        else               cp_wait<0>();
        __syncthreads();
        if (i + 3 < nk) {
            int st2 = (i + 3) & 3;
#pragma unroll
            for (int u = 0; u < LPT; u++)
                cp16(smem_base + (st2*SWORDS + ldst[u])*4, lsrc[u] + (i+3)*32);
            cp_commit();
        }
        uint32_t stw = smem_base + st*SWORDS*4;
        LDFRAG_SM(0, 0);
#pragma unroll
        for (int kk = 0; kk < 2; kk++) {
            int cur = kk & 1;
            if (kk == 0) LDFRAG_SM(1, 1);
#pragma unroll
            for (int ii = 0; ii < 2; ii++)
#pragma unroll
                for (int j = 0; j < 8; j++)
                    mma_bf16(acc[ii][j][0], acc[ii][j][1],
                             acc[ii][j][2], acc[ii][j][3],
                             ar[cur][ii][0], ar[cur][ii][1],
                             ar[cur][ii][2], ar[cur][ii][3],
                             brr[cur][j][0], brr[cur][j][1]);
        }
    }

#pragma unroll
    for (int ii = 0; ii < 2; ii++) {
        int m0 = bm + wm*32 + ii*16 + r0;
#pragma unroll
        for (int j = 0; j < 8; j++) {
            int n0 = wn*64 + j*8 + c0*2;
            *(float2*)&C[(size_t)m0 * XDB + n0]     = make_float2(acc[ii][j][0], acc[ii][j][1]);
            *(float2*)&C[(size_t)(m0+8) * XDB + n0] = make_float2(acc[ii][j][2], acc[ii][j][3]);
        }
    }
}

// ---------------- reduce xproj partials -> bf16 [t][c] + transposed B/C rows ----------------
__global__ __launch_bounds__(256) void reduce_xd()
{
    int br = blockIdx.y;
    int i4 = (blockIdx.x * 256 + threadIdx.x) * 4;
    if (i4 >= TT*XDB) return;
    float4 s = *(const float4*)&g_xdp[br*XSPLIT][i4];
#pragma unroll
    for (int p = 1; p < XSPLIT; p++) {
        float4 a = *(const float4*)&g_xdp[br*XSPLIT + p][i4];
        s.x += a.x; s.y += a.y; s.z += a.z; s.w += a.w;
    }
    *(__nv_bfloat162*)&g_xd_bf[br][i4]   = __float22bfloat162_rn(make_float2(s.x, s.y));
    *(__nv_bfloat162*)&g_xd_bf[br][i4+2] = __float22bfloat162_rn(make_float2(s.z, s.w));
    int c = i4 % XDB;
    if (c >= DTR) {            // B/C columns -> transposed rows
        int t = i4 / XDB;
        int r = c - DTR;
        g_xdT_bf[br][(size_t)(r+0)*TT + t] = __float2bfloat16(s.x);
        g_xdT_bf[br][(size_t)(r+1)*TT + t] = __float2bfloat16(s.y);
        g_xdT_bf[br][(size_t)(r+2)*TT + t] = __float2bfloat16(s.z);
        g_xdT_bf[br][(size_t)(r+3)*TT + t] = __float2bfloat16(s.w);
    }
}

// ---------------- dt GEMM (transposed out): dtT[d][t], M=DI, N=TT, K=96 ----------------
__global__ void __launch_bounds__(256) gemm_dt(
    const __nv_bfloat16* __restrict__ Wt0, const __nv_bfloat16* __restrict__ Wt1, // dtw
    const __nv_bfloat16* __restrict__ Xd0, const __nv_bfloat16* __restrict__ Xd1, // xd
    __nv_bfloat16* __restrict__ C0, __nv_bfloat16* __restrict__ C1,
    const float* __restrict__ bias0, const float* __restrict__ bias1)
{
    constexpr int BMv = 128, THREADS = 256;
    constexpr int SWORDS = (BMv + 128) * 16;
    constexpr int LPT = (BMv + 128) * 4 / THREADS;  // 4
    constexpr int K = DTR;

    extern __shared__ uint32_t sm[];
    uint32_t smem_base = (uint32_t)__cvta_generic_to_shared(sm);

    const __nv_bfloat16* A = blockIdx.z ? Wt1 : Wt0;   // dtw: [DI][96] k-contig
    const __nv_bfloat16* W = blockIdx.z ? Xd1 : Xd0;   // xd : [TT][128], first 96 cols
    __nv_bfloat16* C  = blockIdx.z ? C1 : C0;          // dtT: [DI][TT]
    const float* bias = blockIdx.z ? bias1 : bias0;

    int tid  = threadIdx.x;
    int lane = tid & 31;
    int w    = tid >> 5;
    int wm   = w >> 1;
    int wn   = w & 1;
    int bm   = blockIdx.y * BMv;      // d-dim
    int bn   = blockIdx.x * 128;      // t-dim
    int r0   = lane >> 2;
    int c0   = lane & 3;

    const __nv_bfloat16* lsrc[LPT];
    uint32_t ldst[LPT];
#pragma unroll
    for (int u = 0; u < LPT; u++) {
        int i   = tid + u * THREADS;
        int row = i >> 2;
        int x   = i & 3;
        if (row < BMv) {
            lsrc[u] = A + (size_t)(bm + row) * DTR + x * 8;
            ldst[u] = row * 16 + (x ^ ((row >> 1) & 3)) * 4;
        } else {
            int r = row - BMv;
            lsrc[u] = W + (size_t)(bn + r) * XDB + x * 8;
            ldst[u] = BMv * 16 + r * 16 + (x ^ ((r >> 1) & 3)) * 4;
        }
    }

    constexpr int nk = K / 32;   // 3
#pragma unroll
    for (int p = 0; p < 3; p++) {
#pragma unroll
        for (int u = 0; u < LPT; u++)
            cp16(smem_base + (p*SWORDS + ldst[u])*4, lsrc[u] + p*32);
        cp_commit();
    }

    float acc[2][8][4] = {};
    int arow = lane & 15;
    int ach  = lane >> 4;
    int brow = ((lane >> 4) << 3) + (lane & 7);
    int bch  = (lane >> 3) & 1;

    uint32_t ar[2][2][4];
    uint32_t brr[2][8][2];

    for (int i = 0; i < nk; i++) {
        int st = i & 3;
        int rem = nk - 1 - i;
        if (rem >= 2)      cp_wait<2>();
        else if (rem == 1) cp_wait<1>();
        else               cp_wait<0>();
        __syncthreads();
        uint32_t stw = smem_base + st*SWORDS*4;
        LDFRAG_SM(0, 0);
#pragma unroll
        for (int kk = 0; kk < 2; kk++) {
            int cur = kk & 1;
            if (kk == 0) LDFRAG_SM(1, 1);
#pragma unroll
            for (int ii = 0; ii < 2; ii++)
#pragma unroll
                for (int j = 0; j < 8; j++)
                    mma_bf16(acc[ii][j][0], acc[ii][j][1],
                             acc[ii][j][2], acc[ii][j][3],
                             ar[cur][ii][0], ar[cur][ii][1],
                             ar[cur][ii][2], ar[cur][ii][3],
                             brr[cur][j][0], brr[cur][j][1]);
        }
    }

#pragma unroll
    for (int ii = 0; ii < 2; ii++) {
        int m0 = bm + wm*32 + ii*16 + r0;     // d index
        float bm0 = bias[m0], bm8 = bias[m0+8];
#pragma unroll
        for (int j = 0; j < 8; j++) {
            int n0 = bn + wn*64 + j*8 + c0*2; // t index
            float v0 = acc[ii][j][0] + bm0, v1 = acc[ii][j][1] + bm0;
            float v2 = acc[ii][j][2] + bm8, v3 = acc[ii][j][3] + bm8;
            v0 = fmaxf(v0, 0.f) + log1pf(__expf(-fabsf(v0)));
            v1 = fmaxf(v1, 0.f) + log1pf(__expf(-fabsf(v1)));
            v2 = fmaxf(v2, 0.f) + log1pf(__expf(-fabsf(v2)));
            v3 = fmaxf(v3, 0.f) + log1pf(__expf(-fabsf(v3)));
            *(uint32_t*)&C[(size_t)m0 * TT + n0]     = pk2(v0, v1);
            *(uint32_t*)&C[(size_t)(m0+8) * TT + n0] = pk2(v2, v3);
        }
    }
}

// ------- conv (K=4) + silu; bf16 in; writes xc [t][d] AND xcT [d][t] ------
__global__ __launch_bounds__(256) void conv_silu(
    const float* __restrict__ cw0, const float* __restrict__ cb0,
    const float* __restrict__ cw1, const float* __restrict__ cb1)
{
    int br = blockIdx.y;
    const float* cw = br ? cw1 : cw0;
    const float* cb = br ? cb1 : cb0;
    const __nv_bfloat16* xz = g_xz_bf[br];

    constexpr int ND4 = DI/4;
    int idx = blockIdx.x * 256 + threadIdx.x;
    if (idx >= (TT/4)*ND4) return;
    int tq = idx / ND4;
    int d4 = (idx % ND4) * 4;
    int t0 = tq * 4;
    int l0 = t0 % Lseq;

    float4 wr[4];
#pragma unroll
    for (int i = 0; i < 4; i++) wr[i] = *(const float4*)&cw[(d4+i)*4];
    float4 b4 = *(const float4*)&cb[d4];

    float X[7][4];
    if (br == 0) {
#pragma unroll
        for (int j = 0; j < 7; j++) {
            int off = j - 3;
            if (l0 + off >= 0) ld4bf(&xz[(size_t)(t0+off)*2*DI + d4], X[j]);
            else { X[j][0]=X[j][1]=X[j][2]=X[j][3]=0.f; }
        }
    } else {
#pragma unroll
        for (int j = 0; j < 7; j++) {
            if (l0 + j < Lseq) ld4bf(&xz[(size_t)(t0+j)*2*DI + d4], X[j]);
            else { X[j][0]=X[j][1]=X[j][2]=X[j][3]=0.f; }
        }
    }

    const float* Wp = (const float*)wr;
    const float* Bp = (const float*)&b4;
    float oT[4][4];   // [t][c]
#pragma unroll
    for (int i2 = 0; i2 < 4; i2++) {
#pragma unroll
        for (int c = 0; c < 4; c++) {
            float a = Bp[c];
            if (br == 0) {
                a = fmaf(Wp[c*4+0], X[i2][c],   a);
                a = fmaf(Wp[c*4+1], X[i2+1][c], a);
                a = fmaf(Wp[c*4+2], X[i2+2][c], a);
                a = fmaf(Wp[c*4+3], X[i2+3][c], a);
            } else {
                a = fmaf(Wp[c*4+3], X[i2][c],   a);
                a = fmaf(Wp[c*4+2], X[i2+1][c], a);
                a = fmaf(Wp[c*4+1], X[i2+2][c], a);
                a = fmaf(Wp[c*4+0], X[i2+3][c], a);
            }
            float sg = 1.f / (1.f + __expf(-a));
            oT[i2][c] = a * sg;
        }
        int t = t0 + i2;
        *(__nv_bfloat162*)&g_xc_bf[br][(size_t)t*DI + d4] =
            __float22bfloat162_rn(make_float2(oT[i2][0], oT[i2][1]));
        *(__nv_bfloat162*)&g_xc_bf[br][(size_t)t*DI + d4 + 2] =
            __float22bfloat162_rn(make_float2(oT[i2][2], oT[i2][3]));
    }
    // transposed: per channel, 4 consecutive t
#pragma unroll
    for (int c = 0; c < 4; c++) {
        uint2 v;
        v.x = pk2(oT[0][c], oT[1][c]);
        v.y = pk2(oT[2][c], oT[3][c]);
        *(uint2*)&g_xcT_bf[br][(size_t)(d4+c)*TT + t0] = v;
    }
}

// ---------------- selective scan: transposed bf16 in, vector loads ----------------
__global__ __launch_bounds__(128) void scan_kernel(
    const float* __restrict__ Alog0, const float* __restrict__ Alog1,
    const float* __restrict__ Dv0,   const float* __restrict__ Dv1)
{
    int br = blockIdx.z;
    int b  = blockIdx.y;
    const float* Alog = br ? Alog1 : Alog0;
    const float* Dvec = br ? Dv1   : Dv0;
    const __nv_bfloat16* dtT = g_dtT_bf[br];
    const __nv_bfloat16* xcT = g_xcT_bf[br];
    const __nv_bfloat16* bcT = g_xdT_bf[br];
    float* yo = g_ycf[br];

    int lane = threadIdx.x & 31;
    int warp = threadIdx.x >> 5;
    int n    = lane & 15;
    int d    = blockIdx.x * 8 + warp * 2 + (lane >> 4);

    float A  = -__expf(Alog[d*NS + n]);
    float Dp = Dvec[d];
    float h  = 0.f;

    int step = br ? -1 : 1;
    int jm   = br ? 7 : 0;
    int t    = b*Lseq + (br ? Lseq-1 : 0);   // first-step token
    int tb   = br ? (t - 7) : t;             // batch base (aligned)

    const __nv_bfloat16* pdt = dtT + (size_t)d*TT;
    const __nv_bfloat16* pxc = xcT + (size_t)d*TT;
    const __nv_bfloat16* pB  = bcT + (size_t)n*TT;
    const __nv_bfloat16* pC  = bcT + (size_t)(NS + n)*TT;

    float dt8[8], xv8[8], Bv8[8], Cv8[8];
    ld8bf(pdt + tb, dt8);
    ld8bf(pxc + tb, xv8);
    ld8bf(pB  + tb, Bv8);
    ld8bf(pC  + tb, Cv8);

    for (int s = 0; s < Lseq; s += 8) {
        float nd[8], nx[8], nB[8], nC[8];
        int tbn = tb + 8*step;
        if (s + 8 < Lseq) {
            ld8bf(pdt + tbn, nd);
            ld8bf(pxc + tbn, nx);
            ld8bf(pB  + tbn, nB);
            ld8bf(pC  + tbn, nC);
        } else {
#pragma unroll
            for (int j = 0; j < 8; j++) { nd[j]=0.f; nx[j]=0.f; nB[j]=0.f; nC[j]=0.f; }
        }
        float ya[8];
#pragma unroll
        for (int j = 0; j < 8; j++) {
            int jj = j ^ jm;
            float a = __expf(dt8[jj] * A);
            h = fmaf(a, h, dt8[jj] * xv8[jj] * Bv8[jj]);
            ya[j] = h * Cv8[jj];
        }
#pragma unroll
        for (int off = 8; off; off >>= 1) {
#pragma unroll
            for (int j = 0; j < 8; j++)
                ya[j] += __shfl_xor_sync(0xffffffffu, ya[j], off);
        }
        if (n == 0) {
#pragma unroll
            for (int j = 0; j < 8; j++) {
                int tj = t + j*step;
                yo[(size_t)tj*DI + d] = fmaf(xv8[j ^ jm], Dp, ya[j]);
            }
        }
#pragma unroll
        for (int j = 0; j < 8; j++) {
            dt8[j] = nd[j]; xv8[j] = nx[j]; Bv8[j] = nB[j]; Cv8[j] = nC[j];
        }
        t += 8*step;
        tb = tbn;
    }
}

// ---------------- gate: ycat_bf = ycf * silu(z) ----------------
__global__ __launch_bounds__(256) void gate_kernel()
{
    int br = blockIdx.y;
    int i4 = (blockIdx.x * 256 + threadIdx.x) * 4;
    if (i4 >= TT*DI) return;
    int t = i4 / DI;
    int d = i4 % DI;
    float4 y = *(const float4*)&g_ycf[br][i4];
    float zf[4];
    ld4bf(&g_xz_bf[br][(size_t)t*2*DI + DI + d], zf);
    float o[4];
    const float* yp = (const float*)&y;
#pragma unroll
    for (int i = 0; i < 4; i++) {
        float sz = zf[i] / (1.f + __expf(-zf[i]));
        o[i] = yp[i] * sz;
    }
    __nv_bfloat16* dst = &g_ycat_bf[(size_t)t*2*DI + br*DI + d];
    *(__nv_bfloat162*)dst       = __float22bfloat162_rn(make_float2(o[0], o[1]));
    *(__nv_bfloat162*)(dst + 2) = __float22bfloat162_rn(make_float2(o[2], o[3]));
}

// ---------------- launcher ----------------
extern "C" void kernel_launch(void* const* d_in, const int* in_sizes, int n_in,
                              void* d_out, int out_size)
{
    const float* u       = (const float*)d_in[0];
    const float* norm_w  = (const float*)d_in[1];
    const float* norm_b  = (const float*)d_in[2];
    const float* f_in_w  = (const float*)d_in[3];
    const float* f_cw    = (const float*)d_in[4];
    const float* f_cb    = (const float*)d_in[5];
    const float* f_Alog  = (const float*)d_in[6];
    const float* f_xpw   = (const float*)d_in[7];
    const float* f_dtw   = (const float*)d_in[8];
    const float* f_dtb   = (const float*)d_in[9];
    const float* f_D     = (const float*)d_in[10];
    const float* b_in_w  = (const float*)d_in[11];
    const float* b_cw    = (const float*)d_in[12];
    const float* b_cb    = (const float*)d_in[13];
    const float* b_Alog  = (const float*)d_in[14];
    const float* b_xpw   = (const float*)d_in[15];
    const float* b_dtw   = (const float*)d_in[16];
    const float* b_dtb   = (const float*)d_in[17];
    const float* b_D     = (const float*)d_in[18];
    const float* out_w   = (const float*)d_in[19];
    float* out = (float*)d_out;

    float *xdp, *odp;
    __nv_bfloat16 *un_bf, *xz_bf, *xc_bf, *xd_bf, *dtT_bf, *ycat_bf;
    __nv_bfloat16 *inw_bf, *xpw_bf, *dtw_bf, *outw_bf;
    cudaGetSymbolAddress((void**)&xdp,    g_xdp);
    cudaGetSymbolAddress((void**)&odp,    g_odp);
    cudaGetSymbolAddress((void**)&un_bf,  g_un_bf);
    cudaGetSymbolAddress((void**)&xz_bf,  g_xz_bf);
    cudaGetSymbolAddress((void**)&xc_bf,  g_xc_bf);
    cudaGetSymbolAddress((void**)&xd_bf,  g_xd_bf);
    cudaGetSymbolAddress((void**)&dtT_bf, g_dtT_bf);
    cudaGetSymbolAddress((void**)&ycat_bf,g_ycat_bf);
    cudaGetSymbolAddress((void**)&inw_bf, g_inw_bf);
    cudaGetSymbolAddress((void**)&xpw_bf, g_xpw_bf);
    cudaGetSymbolAddress((void**)&dtw_bf, g_dtw_bf);
    cudaGetSymbolAddress((void**)&outw_bf,g_outw_bf);

    __nv_bfloat16* xzb0 = xz_bf;  __nv_bfloat16* xzb1 = xz_bf + (size_t)TT*2*DI;
    __nv_bfloat16* xcb0 = xc_bf;  __nv_bfloat16* xcb1 = xc_bf + (size_t)TT*DI;
    __nv_bfloat16* xdb0 = xd_bf;  __nv_bfloat16* xdb1 = xd_bf + (size_t)TT*XDB;
    __nv_bfloat16* dtT0 = dtT_bf; __nv_bfloat16* dtT1 = dtT_bf + (size_t)DI*TT;
    __nv_bfloat16* inw0 = inw_bf; __nv_bfloat16* inw1 = inw_bf + (size_t)IN_W;
    __nv_bfloat16* xpw0 = xpw_bf; __nv_bfloat16* xpw1 = xpw_bf + (size_t)XP_W;
    __nv_bfloat16* dtw0 = dtw_bf; __nv_bfloat16* dtw1 = dtw_bf + (size_t)DT_W;

    constexpr int SM_BIG = 3 * 32768;
    constexpr int SM_XP  = 4 * 192 * 64;
    constexpr int SM_DT  = 4 * 256 * 64;
    cudaFuncSetAttribute((const void*)gemm_big<0>,
        cudaFuncAttributeMaxDynamicSharedMemorySize, SM_BIG);
    cudaFuncSetAttribute((const void*)gemm_big<3>,
        cudaFuncAttributeMaxDynamicSharedMemorySize, SM_BIG);
    cudaFuncSetAttribute((const void*)gemm_xp,
        cudaFuncAttributeMaxDynamicSharedMemorySize, SM_XP);
    cudaFuncSetAttribute((const void*)gemm_dt,
        cudaFuncAttributeMaxDynamicSharedMemorySize, SM_DT);

    // 0) weights->bf16 + layernorm (merged)
    prep_kernel<<<NCVT + TT, 256>>>(u, norm_w, norm_b,
                                    f_in_w, b_in_w, f_xpw, b_xpw,
                                    f_dtw, b_dtw, out_w);

    // 1) in-proj -> bf16 xz
    gemm_big<0><<<dim3(2*DI/128, TT/128, 2), 128, SM_BIG>>>(
        un_bf, un_bf, DM, inw0, inw1, DM, nullptr, 2*DI, xzb0, xzb1, DM);

    // 2) conv + silu -> xc [t][d] + xcT [d][t]
    conv_silu<<<dim3((TT/4)*(DI/4)/256, 2), 256>>>(f_cw, f_cb, b_cw, b_cb);

    // 3) xproj split-K x4 + reduce -> xd [t][c] + xdT B/C rows
    gemm_xp<<<dim3(1, TT/64, 2*XSPLIT), 128, SM_XP>>>(
        xcb0, xcb1, xpw0, xpw1, xdp);
    reduce_xd<<<dim3(TT*XDB/4/256, 2), 256>>>();

    // 4) dt (transposed out): dtT[d][t], softplus+bias on d
    gemm_dt<<<dim3(TT/128, DI/128, 2), 256, SM_DT>>>(
        dtw0, dtw1, xdb0, xdb1, dtT0, dtT1, f_dtb, b_dtb);

    // 5) selective scan (transposed vector loads) -> fp32 ycf
    scan_kernel<<<dim3(DI/8, Bb, 2), 128>>>(f_Alog, b_Alog, f_D, b_D);

    // 6) gate
    gate_kernel<<<dim3(TT*DI/4/256, 2), 256>>>();

    // 7) out-proj split-K x2 -> partials, then reduce + residual
    gemm_big<3><<<dim3(DM/128, TT/128, OSPLIT), 128, SM_BIG>>>(
        ycat_bf, nullptr, 2*DI, outw_bf, nullptr, 2*DI, odp, DM,
        nullptr, nullptr, (2*DI)/OSPLIT);
    reduce_out<<<TT*DM/4/256, 256>>>(u, out);
}

// round 16
// speedup vs baseline: 1.3745x; 1.3745x over previous
#include <cuda_runtime.h>
#include <cuda_bf16.h>
#include <math.h>
#include <stdint.h>

#define Bb   2
#define Lseq 1024
#define DM   768
#define DI   1536
#define NS   16
#define DTR  96
#define XDB  (DTR + 2*NS)   // 128
#define TT   (Bb*Lseq)      // 2048

#define IN_W  (2*DI*DM)
#define XP_W  (XDB*DI)
#define DT_W  (DI*DTR)
#define OUT_W (DM*2*DI)
#define WTOT  (2*IN_W + 2*XP_W + 2*DT_W + OUT_W)   // 7766016
#define NCVT  (WTOT/8/256)                          // 3792 blocks
#define OSPLIT 3
#define XSPLIT 4

// ---------------- fp32 scratch ----------------
__device__ float g_xdp[2*XSPLIT][TT*XDB];
__device__ float g_odp[OSPLIT][TT*DM];
__device__ float g_ycf[2][TT*DI];
// ---------------- bf16 scratch ----------------
__device__ __nv_bfloat16 g_un_bf[TT*DM];
__device__ __nv_bfloat16 g_xz_bf[2][TT*2*DI];
__device__ __nv_bfloat16 g_xc_bf[2][TT*DI];
__device__ __nv_bfloat16 g_xd_bf[2][TT*XDB];
__device__ __nv_bfloat16 g_dt_bf[2][TT*DI];
__device__ __nv_bfloat16 g_ycat_bf[TT*2*DI];
__device__ __nv_bfloat16 g_inw_bf[2][IN_W];
__device__ __nv_bfloat16 g_xpw_bf[2][XP_W];
__device__ __nv_bfloat16 g_dtw_bf[2][DT_W];
__device__ __nv_bfloat16 g_outw_bf[OUT_W];

// ---------------- helpers ----------------
__device__ __forceinline__ void cp16(uint32_t dst_s, const void* src) {
    asm volatile("cp.async.ca.shared.global [%0], [%1], 16;\n" :: "r"(dst_s), "l"(src));
}
__device__ __forceinline__ void cp_commit() {
    asm volatile("cp.async.commit_group;\n");
}
template<int N> __device__ __forceinline__ void cp_wait() {
    asm volatile("cp.async.wait_group %0;\n" :: "n"(N));
}
__device__ __forceinline__ void ldsm4(uint32_t& r0, uint32_t& r1,
                                      uint32_t& r2, uint32_t& r3, uint32_t a) {
    asm volatile("ldmatrix.sync.aligned.m8n8.x4.shared.b16 {%0,%1,%2,%3}, [%4];\n"
        : "=r"(r0), "=r"(r1), "=r"(r2), "=r"(r3) : "r"(a));
}
__device__ __forceinline__ void mma_bf16(
    float& c0, float& c1, float& c2, float& c3,
    uint32_t a0, uint32_t a1, uint32_t a2, uint32_t a3,
    uint32_t b0, uint32_t b1)
{
    asm volatile(
        "mma.sync.aligned.m16n8k16.row.col.f32.bf16.bf16.f32 "
        "{%0,%1,%2,%3}, {%4,%5,%6,%7}, {%8,%9}, {%0,%1,%2,%3};\n"
        : "+f"(c0), "+f"(c1), "+f"(c2), "+f"(c3)
        : "r"(a0), "r"(a1), "r"(a2), "r"(a3), "r"(b0), "r"(b1));
}
__device__ __forceinline__ uint32_t pk2(float a, float b) {
    __nv_bfloat162 h = __float22bfloat162_rn(make_float2(a, b));
    return *reinterpret_cast<uint32_t*>(&h);
}
__device__ __forceinline__ void ld4bf(const __nv_bfloat16* p, float* o) {
    uint2 r = *(const uint2*)p;
    __nv_bfloat162 lo = *reinterpret_cast<__nv_bfloat162*>(&r.x);
    __nv_bfloat162 hi = *reinterpret_cast<__nv_bfloat162*>(&r.y);
    float2 f0 = __bfloat1622float2(lo);
    float2 f1 = __bfloat1622float2(hi);
    o[0] = f0.x; o[1] = f0.y; o[2] = f1.x; o[3] = f1.y;
}

// ---------------- prep: weight cvt + layernorm ----------------
__global__ __launch_bounds__(256) void prep_kernel(
    const float* __restrict__ u, const float* __restrict__ nw,
    const float* __restrict__ nb,
    const float* __restrict__ fw, const float* __restrict__ bw,
    const float* __restrict__ fx, const float* __restrict__ bx,
    const float* __restrict__ fd, const float* __restrict__ bd,
    const float* __restrict__ ow)
{
    if (blockIdx.x < NCVT) {
        long long i = ((long long)blockIdx.x * 256 + threadIdx.x) * 8;
        const float* s; __nv_bfloat16* dst;
        if (i < IN_W)                 { s = fw + i; dst = &g_inw_bf[0][i]; }
        else if ((i -= IN_W) < IN_W)  { s = bw + i; dst = &g_inw_bf[1][i]; }
        else if ((i -= IN_W) < XP_W)  { s = fx + i; dst = &g_xpw_bf[0][i]; }
        else if ((i -= XP_W) < XP_W)  { s = bx + i; dst = &g_xpw_bf[1][i]; }
        else if ((i -= XP_W) < DT_W)  { s = fd + i; dst = &g_dtw_bf[0][i]; }
        else if ((i -= DT_W) < DT_W)  { s = bd + i; dst = &g_dtw_bf[1][i]; }
        else if ((i -= DT_W) < OUT_W) { s = ow + i; dst = &g_outw_bf[i]; }
        else return;
        float4 lo = *(const float4*)s;
        float4 hi = *(const float4*)(s + 4);
        uint4 o;
        o.x = pk2(lo.x, lo.y); o.y = pk2(lo.z, lo.w);
        o.z = pk2(hi.x, hi.y); o.w = pk2(hi.z, hi.w);
        *(uint4*)dst = o;
        return;
    }
    int t = blockIdx.x - NCVT;
    const float* row = u + (size_t)t * DM;
    float v[3];
    float s = 0.f, s2 = 0.f;
#pragma unroll
    for (int i = 0; i < 3; i++) {
        v[i] = row[threadIdx.x + i*256];
        s  += v[i];
        s2 += v[i]*v[i];
    }
#pragma unroll
    for (int o = 16; o; o >>= 1) {
        s  += __shfl_xor_sync(0xffffffffu, s,  o);
        s2 += __shfl_xor_sync(0xffffffffu, s2, o);
    }
    __shared__ float ss[8], ss2[8];
    int wid = threadIdx.x >> 5, ln = threadIdx.x & 31;
    if (ln == 0) { ss[wid] = s; ss2[wid] = s2; }
    __syncthreads();
    float ts = 0.f, ts2 = 0.f;
#pragma unroll
    for (int i = 0; i < 8; i++) { ts += ss[i]; ts2 += ss2[i]; }
    float mu  = ts * (1.f/DM);
    float var = ts2 * (1.f/DM) - mu*mu;
    float rs  = rsqrtf(var + 1e-5f);
#pragma unroll
    for (int i = 0; i < 3; i++) {
        int c = threadIdx.x + i*256;
        g_un_bf[(size_t)t*DM + c] = __float2bfloat16((v[i]-mu)*rs*nw[c] + nb[c]);
    }
}

// fragment-load macro (double-buffered) for gemm_big
#define LDFRAG_BIG(B, KK) do {                                                \
    _Pragma("unroll")                                                         \
    for (int ii = 0; ii < 4; ii++) {                                          \
        int row = wm*64 + ii*16 + arow;                                       \
        int pos = (2*(KK) + ach) ^ (row & 7);                                 \
        ldsm4(ar[B][ii][0], ar[B][ii][1], ar[B][ii][2], ar[B][ii][3],         \
              base + row*128 + pos*16);                                       \
    }                                                                         \
    _Pragma("unroll")                                                         \
    for (int j2 = 0; j2 < 4; j2++) {                                          \
        int row = wn*64 + j2*16 + brow;                                       \
        int pos = (2*(KK) + bch) ^ (row & 7);                                 \
        ldsm4(brr[B][2*j2][0], brr[B][2*j2][1],                               \
              brr[B][2*j2+1][0], brr[B][2*j2+1][1],                           \
              base + 16384 + row*128 + pos*16);                               \
    }                                                                         \
} while (0)

// ======== gemm_big: 128x128 CTA tile, 4 warps (64x64 each), k64 slabs ========
// MODE 0: bf16 out (z = branch).  MODE 3: split-K fp32 partials (z = k-chunk).
template<int MODE>
__global__ void __launch_bounds__(128) gemm_big(
    const __nv_bfloat16* __restrict__ A0, const __nv_bfloat16* __restrict__ A1, int lda,
    const __nv_bfloat16* __restrict__ W0, const __nv_bfloat16* __restrict__ W1, int ldw,
    float* __restrict__ C0, int ldc,
    __nv_bfloat16* __restrict__ Cb0, __nv_bfloat16* __restrict__ Cb1,
    int K)
{
    extern __shared__ char smem[];
    uint32_t sb = (uint32_t)__cvta_generic_to_shared(smem);

    const __nv_bfloat16* A;
    const __nv_bfloat16* W;
    float* C = nullptr;
    __nv_bfloat16* Cb = nullptr;
    if (MODE == 3) {
        A = A0 + (size_t)blockIdx.z * K;
        W = W0 + (size_t)blockIdx.z * K;
        C = C0 + (size_t)blockIdx.z * ((size_t)TT * DM);
    } else {
        A  = blockIdx.z ? A1 : A0;
        W  = blockIdx.z ? W1 : W0;
        Cb = blockIdx.z ? Cb1 : Cb0;
    }

    int tid  = threadIdx.x;
    int lane = tid & 31;
    int w    = tid >> 5;
    int wm   = w >> 1;
    int wn   = w & 1;
    int bm   = blockIdx.y * 128;
    int bn   = blockIdx.x * 128;

    int ch = tid & 7;
    int rb = tid >> 3;
    const __nv_bfloat16* ap = A + (size_t)(bm + rb) * lda + ch * 8;
    const __nv_bfloat16* wp = W + (size_t)(bn + rb) * ldw + ch * 8;
    uint32_t ao = (uint32_t)(rb * 128 + ((ch ^ (rb & 7)) * 16));
    uint32_t bo = 16384u + ao;

    int nk = K / 64;
#pragma unroll
    for (int p = 0; p < 2; p++) {
#pragma unroll
        for (int v = 0; v < 8; v++) {
            cp16(sb + p*32768 + ao + v*2048, ap + (size_t)v*16*lda + p*64);
            cp16(sb + p*32768 + bo + v*2048, wp + (size_t)v*16*ldw + p*64);
        }
        cp_commit();
    }

    float acc[4][8][4] = {};
    int arow = lane & 15;
    int ach  = lane >> 4;
    int brow = ((lane >> 4) << 3) + (lane & 7);
    int bch  = (lane >> 3) & 1;
    int r0   = lane >> 2;
    int c0   = lane & 3;

    uint32_t ar[2][4][4];
    uint32_t brr[2][8][2];

    for (int i = 0; i < nk; i++) {
        int st = i % 3;
        cp_wait<1>();
        __syncthreads();
        {
            int s2 = (i + 2) % 3;
            if (i + 2 < nk) {
#pragma unroll
                for (int v = 0; v < 8; v++) {
                    cp16(sb + s2*32768 + ao + v*2048, ap + (size_t)v*16*lda + (i+2)*64);
                    cp16(sb + s2*32768 + bo + v*2048, wp + (size_t)v*16*ldw + (i+2)*64);
                }
            }
            cp_commit();
        }
        uint32_t base = sb + st*32768;
        LDFRAG_BIG(0, 0);
#pragma unroll
        for (int kk = 0; kk < 4; kk++) {
            int cur = kk & 1;
            if (kk == 0) LDFRAG_BIG(1, 1);
            else if (kk == 1) LDFRAG_BIG(0, 2);
            else if (kk == 2) LDFRAG_BIG(1, 3);
#pragma unroll
            for (int ii = 0; ii < 4; ii++)
#pragma unroll
                for (int j = 0; j < 8; j++)
                    mma_bf16(acc[ii][j][0], acc[ii][j][1],
                             acc[ii][j][2], acc[ii][j][3],
                             ar[cur][ii][0], ar[cur][ii][1],
                             ar[cur][ii][2], ar[cur][ii][3],
                             brr[cur][j][0], brr[cur][j][1]);
        }
    }

#pragma unroll
    for (int ii = 0; ii < 4; ii++) {
        int m0 = bm + wm*64 + ii*16 + r0;
#pragma unroll
        for (int j = 0; j < 8; j++) {
            int n0 = bn + wn*64 + j*8 + c0*2;
            if (MODE == 3) {
                *(float2*)&C[(size_t)m0 * ldc + n0] =
                    make_float2(acc[ii][j][0], acc[ii][j][1]);
                *(float2*)&C[(size_t)(m0+8) * ldc + n0] =
                    make_float2(acc[ii][j][2], acc[ii][j][3]);
            } else {
                *(uint32_t*)&Cb[(size_t)m0 * ldc + n0] =
                    pk2(acc[ii][j][0], acc[ii][j][1]);
                *(uint32_t*)&Cb[(size_t)(m0+8) * ldc + n0] =
                    pk2(acc[ii][j][2], acc[ii][j][3]);
            }
        }
    }
}

// ---------------- out-proj reduce ----------------
__global__ __launch_bounds__(256) void reduce_out(const float* __restrict__ u,
                                                  float* __restrict__ out)
{
    int i4 = (blockIdx.x * 256 + threadIdx.x) * 4;
    if (i4 >= TT*DM) return;
    float4 s = *(const float4*)&u[i4];
#pragma unroll
    for (int p = 0; p < OSPLIT; p++) {
        float4 a = *(const float4*)&g_odp[p][i4];
        s.x += a.x; s.y += a.y; s.z += a.z; s.w += a.w;
    }
    *(float4*)&out[i4] = s;
}

// frag loads for 32x64-warp-tile kernels (xp, dt)
#define LDFRAG_SM(B, KK) do {                                                 \
    _Pragma("unroll")                                                         \
    for (int ii = 0; ii < 2; ii++) {                                          \
        int row = wm*32 + ii*16 + arow;                                       \
        int pos = (2*(KK) + ach) ^ ((row >> 1) & 3);                          \
        ldsm4(ar[B][ii][0], ar[B][ii][1], ar[B][ii][2], ar[B][ii][3],         \
              stw + (row*16 + pos*4)*4);                                      \
    }                                                                         \
    _Pragma("unroll")                                                         \
    for (int j2 = 0; j2 < 4; j2++) {                                          \
        int row = wn*64 + j2*16 + brow;                                       \
        int pos = (2*(KK) + bch) ^ ((row >> 1) & 3);                          \
        ldsm4(brr[B][2*j2][0], brr[B][2*j2][1],                               \
              brr[B][2*j2+1][0], brr[B][2*j2+1][1],                           \
              stw + (BMv*16 + row*16 + pos*4)*4);                             \
    }                                                                         \
} while (0)

// ======== gemm_xp: xproj split-K x4.  BM=64, BN=128, 4 warps (32x64), K=384 ========
__global__ void __launch_bounds__(128) gemm_xp(
    const __nv_bfloat16* __restrict__ Ab0, const __nv_bfloat16* __restrict__ Ab1,
    const __nv_bfloat16* __restrict__ Wb0, const __nv_bfloat16* __restrict__ Wb1,
    float* __restrict__ Cp)
{
    constexpr int BMv = 64, THREADS = 128;
    constexpr int SWORDS = (BMv + 128) * 16;
    constexpr int LPT = (BMv + 128) * 4 / THREADS;  // 6
    constexpr int KPART = DI / XSPLIT;              // 384

    extern __shared__ uint32_t sm[];
    uint32_t smem_base = (uint32_t)__cvta_generic_to_shared(sm);

    int z  = blockIdx.z;
    int br = z >> 2;
    int kp = z & 3;
    const __nv_bfloat16* A = (br ? Ab1 : Ab0) + kp * KPART;
    const __nv_bfloat16* W = (br ? Wb1 : Wb0) + kp * KPART;
    float* C = Cp + (size_t)z * (TT*XDB);

    int tid  = threadIdx.x;
    int lane = tid & 31;
    int w    = tid >> 5;
    int wm   = w >> 1;
    int wn   = w & 1;
    int bm   = blockIdx.y * BMv;
    int r0   = lane >> 2;
    int c0   = lane & 3;

    const __nv_bfloat16* lsrc[LPT];
    uint32_t ldst[LPT];
#pragma unroll
    for (int u = 0; u < LPT; u++) {
        int i   = tid + u * THREADS;
        int row = i >> 2;
        int x   = i & 3;
        if (row < BMv) {
            lsrc[u] = A + (size_t)(bm + row) * DI + x * 8;
            ldst[u] = row * 16 + (x ^ ((row >> 1) & 3)) * 4;
        } else {
            int r = row - BMv;
            lsrc[u] = W + (size_t)r * DI + x * 8;
            ldst[u] = BMv * 16 + r * 16 + (x ^ ((r >> 1) & 3)) * 4;
        }
    }

    constexpr int nk = KPART / 32;   // 12
#pragma unroll
    for (int p = 0; p < 3; p++) {
#pragma unroll
        for (int u = 0; u < LPT; u++)
            cp16(smem_base + (p*SWORDS + ldst[u])*4, lsrc[u] + p*32);
        cp_commit();
    }

    float acc[2][8][4] = {};
    int arow = lane & 15;
    int ach  = lane >> 4;
    int brow = ((lane >> 4) << 3) + (lane & 7);
    int bch  = (lane >> 3) & 1;

    uint32_t ar[2][2][4];
    uint32_t brr[2][8][2];

    for (int i = 0; i < nk; i++) {
        int st = i & 3;
        int rem = nk - 1 - i;
        if (rem >= 2)      cp_wait<2>();
        else if (rem == 1) cp_wait<1>();
        else               cp_wait<0>();
        __syncthreads();
        if (i + 3 < nk) {
            int st2 = (i + 3) & 3;
#pragma unroll
            for (int u = 0; u < LPT; u++)
                cp16(smem_base + (st2*SWORDS + ldst[u])*4, lsrc[u] + (i+3)*32);
            cp_commit();
        }
        uint32_t stw = smem_base + st*SWORDS*4;
        LDFRAG_SM(0, 0);
#pragma unroll
        for (int kk = 0; kk < 2; kk++) {
            int cur = kk & 1;
            if (kk == 0) LDFRAG_SM(1, 1);
#pragma unroll
            for (int ii = 0; ii < 2; ii++)
#pragma unroll
                for (int j = 0; j < 8; j++)
                    mma_bf16(acc[ii][j][0], acc[ii][j][1],
                             acc[ii][j][2], acc[ii][j][3],
                             ar[cur][ii][0], ar[cur][ii][1],
                             ar[cur][ii][2], ar[cur][ii][3],
                             brr[cur][j][0], brr[cur][j][1]);
        }
    }

#pragma unroll
    for (int ii = 0; ii < 2; ii++) {
        int m0 = bm + wm*32 + ii*16 + r0;
#pragma unroll
        for (int j = 0; j < 8; j++) {
            int n0 = wn*64 + j*8 + c0*2;
            *(float2*)&C[(size_t)m0 * XDB + n0]     = make_float2(acc[ii][j][0], acc[ii][j][1]);
            *(float2*)&C[(size_t)(m0+8) * XDB + n0] = make_float2(acc[ii][j][2], acc[ii][j][3]);
        }
    }
}

// ---------------- reduce xproj partials -> bf16 ----------------
__global__ __launch_bounds__(256) void reduce_xd()
{
    int br = blockIdx.y;
    int i4 = (blockIdx.x * 256 + threadIdx.x) * 4;
    if (i4 >= TT*XDB) return;
    float4 s = *(const float4*)&g_xdp[br*XSPLIT][i4];
#pragma unroll
    for (int p = 1; p < XSPLIT; p++) {
        float4 a = *(const float4*)&g_xdp[br*XSPLIT + p][i4];
        s.x += a.x; s.y += a.y; s.z += a.z; s.w += a.w;
    }
    *(__nv_bfloat162*)&g_xd_bf[br][i4]   = __float22bfloat162_rn(make_float2(s.x, s.y));
    *(__nv_bfloat162*)&g_xd_bf[br][i4+2] = __float22bfloat162_rn(make_float2(s.z, s.w));
}

// ---------------- dt GEMM: 128x128, K=96, softplus, bf16 out ----------------
__global__ void __launch_bounds__(256) gemm_dt(
    const __nv_bfloat16* __restrict__ A0, const __nv_bfloat16* __restrict__ A1,
    const __nv_bfloat16* __restrict__ W0, const __nv_bfloat16* __restrict__ W1,
    __nv_bfloat16* __restrict__ C0, __nv_bfloat16* __restrict__ C1,
    const float* __restrict__ bias0, const float* __restrict__ bias1)
{
    constexpr int BMv = 128, THREADS = 256;
    constexpr int SWORDS = (BMv + 128) * 16;
    constexpr int LPT = (BMv + 128) * 4 / THREADS;  // 4
    constexpr int K = DTR;

    extern __shared__ uint32_t sm[];
    uint32_t smem_base = (uint32_t)__cvta_generic_to_shared(sm);

    const __nv_bfloat16* A = blockIdx.z ? A1 : A0;
    const __nv_bfloat16* W = blockIdx.z ? W1 : W0;
    __nv_bfloat16* C  = blockIdx.z ? C1 : C0;
    const float* bias = blockIdx.z ? bias1 : bias0;

    int tid  = threadIdx.x;
    int lane = tid & 31;
    int w    = tid >> 5;
    int wm   = w >> 1;
    int wn   = w & 1;
    int bm   = blockIdx.y * BMv;
    int bn   = blockIdx.x * 128;
    int r0   = lane >> 2;
    int c0   = lane & 3;

    const __nv_bfloat16* lsrc[LPT];
    uint32_t ldst[LPT];
#pragma unroll
    for (int u = 0; u < LPT; u++) {
        int i   = tid + u * THREADS;
        int row = i >> 2;
        int x   = i & 3;
        if (row < BMv) {
            lsrc[u] = A + (size_t)(bm + row) * XDB + x * 8;
            ldst[u] = row * 16 + (x ^ ((row >> 1) & 3)) * 4;
        } else {
            int r = row - BMv;
            lsrc[u] = W + (size_t)(bn + r) * DTR + x * 8;
            ldst[u] = BMv * 16 + r * 16 + (x ^ ((r >> 1) & 3)) * 4;
        }
    }

    constexpr int nk = K / 32;   // 3
#pragma unroll
    for (int p = 0; p < 3; p++) {
#pragma unroll
        for (int u = 0; u < LPT; u++)
            cp16(smem_base + (p*SWORDS + ldst[u])*4, lsrc[u] + p*32);
        cp_commit();
    }

    float acc[2][8][4] = {};
    int arow = lane & 15;
    int ach  = lane >> 4;
    int brow = ((lane >> 4) << 3) + (lane & 7);
    int bch  = (lane >> 3) & 1;

    uint32_t ar[2][2][4];
    uint32_t brr[2][8][2];

    for (int i = 0; i < nk; i++) {
        int st = i & 3;
        int rem = nk - 1 - i;
        if (rem >= 2)      cp_wait<2>();
        else if (rem == 1) cp_wait<1>();
        else               cp_wait<0>();
        __syncthreads();
        uint32_t stw = smem_base + st*SWORDS*4;
        LDFRAG_SM(0, 0);
#pragma unroll
        for (int kk = 0; kk < 2; kk++) {
            int cur = kk & 1;
            if (kk == 0) LDFRAG_SM(1, 1);
#pragma unroll
            for (int ii = 0; ii < 2; ii++)
#pragma unroll
                for (int j = 0; j < 8; j++)
                    mma_bf16(acc[ii][j][0], acc[ii][j][1],
                             acc[ii][j][2], acc[ii][j][3],
                             ar[cur][ii][0], ar[cur][ii][1],
                             ar[cur][ii][2], ar[cur][ii][3],
                             brr[cur][j][0], brr[cur][j][1]);
        }
    }

#pragma unroll
    for (int ii = 0; ii < 2; ii++) {
        int m0 = bm + wm*32 + ii*16 + r0;
#pragma unroll
        for (int j = 0; j < 8; j++) {
            int n0 = bn + wn*64 + j*8 + c0*2;
            float v0 = acc[ii][j][0], v1 = acc[ii][j][1];
            float v2 = acc[ii][j][2], v3 = acc[ii][j][3];
            float b0v = bias[n0], b1v = bias[n0 + 1];
            v0 += b0v; v1 += b1v; v2 += b0v; v3 += b1v;
            v0 = fmaxf(v0, 0.f) + log1pf(__expf(-fabsf(v0)));
            v1 = fmaxf(v1, 0.f) + log1pf(__expf(-fabsf(v1)));
            v2 = fmaxf(v2, 0.f) + log1pf(__expf(-fabsf(v2)));
            v3 = fmaxf(v3, 0.f) + log1pf(__expf(-fabsf(v3)));
            *(uint32_t*)&C[(size_t)m0 * DI + n0]     = pk2(v0, v1);
            *(uint32_t*)&C[(size_t)(m0+8) * DI + n0] = pk2(v2, v3);
        }
    }
}

// ------- conv (K=4) + silu; bf16 in/out; 4 tokens x 4 ch ------
__global__ __launch_bounds__(256) void conv_silu(
    const float* __restrict__ cw0, const float* __restrict__ cb0,
    const float* __restrict__ cw1, const float* __restrict__ cb1)
{
    int br = blockIdx.y;
    const float* cw = br ? cw1 : cw0;
    const float* cb = br ? cb1 : cb0;
    const __nv_bfloat16* xz = g_xz_bf[br];

    constexpr int ND4 = DI/4;
    int idx = blockIdx.x * 256 + threadIdx.x;
    if (idx >= (TT/4)*ND4) return;
    int tq = idx / ND4;
    int d4 = (idx % ND4) * 4;
    int t0 = tq * 4;
    int l0 = t0 % Lseq;

    float4 wr[4];
#pragma unroll
    for (int i = 0; i < 4; i++) wr[i] = *(const float4*)&cw[(d4+i)*4];
    float4 b4 = *(const float4*)&cb[d4];

    float X[7][4];
    if (br == 0) {
#pragma unroll
        for (int j = 0; j < 7; j++) {
            int off = j - 3;
            if (l0 + off >= 0) ld4bf(&xz[(size_t)(t0+off)*2*DI + d4], X[j]);
            else { X[j][0]=X[j][1]=X[j][2]=X[j][3]=0.f; }
        }
    } else {
#pragma unroll
        for (int j = 0; j < 7; j++) {
            if (l0 + j < Lseq) ld4bf(&xz[(size_t)(t0+j)*2*DI + d4], X[j]);
            else { X[j][0]=X[j][1]=X[j][2]=X[j][3]=0.f; }
        }
    }

    const float* Wp = (const float*)wr;
    const float* Bp = (const float*)&b4;
#pragma unroll
    for (int i2 = 0; i2 < 4; i2++) {
        float o[4];
#pragma unroll
        for (int c = 0; c < 4; c++) {
            float a = Bp[c];
            if (br == 0) {
                a = fmaf(Wp[c*4+0], X[i2][c],   a);
                a = fmaf(Wp[c*4+1], X[i2+1][c], a);
                a = fmaf(Wp[c*4+2], X[i2+2][c], a);
                a = fmaf(Wp[c*4+3], X[i2+3][c], a);
            } else {
                a = fmaf(Wp[c*4+3], X[i2][c],   a);
                a = fmaf(Wp[c*4+2], X[i2+1][c], a);
                a = fmaf(Wp[c*4+1], X[i2+2][c], a);
                a = fmaf(Wp[c*4+0], X[i2+3][c], a);
            }
            float sg = 1.f / (1.f + __expf(-a));
            o[c] = a * sg;
        }
        int t = t0 + i2;
        *(__nv_bfloat162*)&g_xc_bf[br][(size_t)t*DI + d4] =
            __float22bfloat162_rn(make_float2(o[0], o[1]));
        *(__nv_bfloat162*)&g_xc_bf[br][(size_t)t*DI + d4 + 2] =
            __float22bfloat162_rn(make_float2(o[2], o[3]));
    }
}

// ---------------- selective scan: bf16 in, 8-step pipelined, fp32 out ----------------
__global__ __launch_bounds__(128) void scan_kernel(
    const float* __restrict__ Alog0, const float* __restrict__ Alog1,
    const float* __restrict__ Dv0,   const float* __restrict__ Dv1)
{
    int br = blockIdx.z;
    int b  = blockIdx.y;
    const float* Alog = br ? Alog1 : Alog0;
    const float* Dvec = br ? Dv1   : Dv0;
    const __nv_bfloat16* dt = g_dt_bf[br];
    const __nv_bfloat16* xc = g_xc_bf[br];
    const __nv_bfloat16* xd = g_xd_bf[br];
    float* yo = g_ycf[br];

    int lane = threadIdx.x & 31;
    int warp = threadIdx.x >> 5;
    int n    = lane & 15;
    int d    = blockIdx.x * 8 + warp * 2 + (lane >> 4);

    float A  = -__expf(Alog[d*NS + n]);
    float Dp = Dvec[d];
    float h  = 0.f;

    int step = br ? -1 : 1;
    int t = b*Lseq + (br ? Lseq-1 : 0);

    float dt8[8], xv8[8], Bv8[8], Cv8[8];
    {
        int tq = t;
#pragma unroll
        for (int j = 0; j < 8; j++) {
            dt8[j] = __bfloat162float(dt[(size_t)tq*DI + d]);
            xv8[j] = __bfloat162float(xc[(size_t)tq*DI + d]);
            Bv8[j] = __bfloat162float(xd[(size_t)tq*XDB + DTR + n]);
            Cv8[j] = __bfloat162float(xd[(size_t)tq*XDB + DTR + NS + n]);
            tq += step;
        }
    }

    for (int s = 0; s < Lseq; s += 8) {
        float nd[8], nx[8], nB[8], nC[8];
        if (s + 8 < Lseq) {
            int tq = t + 8*step;
#pragma unroll
            for (int j = 0; j < 8; j++) {
                nd[j] = __bfloat162float(dt[(size_t)tq*DI + d]);
                nx[j] = __bfloat162float(xc[(size_t)tq*DI + d]);
                nB[j] = __bfloat162float(xd[(size_t)tq*XDB + DTR + n]);
                nC[j] = __bfloat162float(xd[(size_t)tq*XDB + DTR + NS + n]);
                tq += step;
            }
        } else {
#pragma unroll
            for (int j = 0; j < 8; j++) { nd[j]=0.f; nx[j]=0.f; nB[j]=0.f; nC[j]=0.f; }
        }
        float ya[8];
#pragma unroll
        for (int j = 0; j < 8; j++) {
            float a = __expf(dt8[j] * A);
            h = fmaf(a, h, dt8[j] * xv8[j] * Bv8[j]);
            ya[j] = h * Cv8[j];
        }
#pragma unroll
        for (int off = 8; off; off >>= 1) {
#pragma unroll
            for (int j = 0; j < 8; j++)
                ya[j] += __shfl_xor_sync(0xffffffffu, ya[j], off);
        }
        if (n == 0) {
#pragma unroll
            for (int j = 0; j < 8; j++) {
                int tj = t + j*step;
                yo[(size_t)tj*DI + d] = fmaf(xv8[j], Dp, ya[j]);
            }
        }
#pragma unroll
        for (int j = 0; j < 8; j++) {
            dt8[j] = nd[j]; xv8[j] = nx[j]; Bv8[j] = nB[j]; Cv8[j] = nC[j];
        }
        t += 8*step;
    }
}

// ---------------- gate: ycat_bf = ycf * silu(z) ----------------
__global__ __launch_bounds__(256) void gate_kernel()
{
    int br = blockIdx.y;
    int i4 = (blockIdx.x * 256 + threadIdx.x) * 4;
    if (i4 >= TT*DI) return;
    int t = i4 / DI;
    int d = i4 % DI;
    float4 y = *(const float4*)&g_ycf[br][i4];
    float zf[4];
    ld4bf(&g_xz_bf[br][(size_t)t*2*DI + DI + d], zf);
    float o[4];
    const float* yp = (const float*)&y;
#pragma unroll
    for (int i = 0; i < 4; i++) {
        float sz = zf[i] / (1.f + __expf(-zf[i]));
        o[i] = yp[i] * sz;
    }
    __nv_bfloat16* dst = &g_ycat_bf[(size_t)t*2*DI + br*DI + d];
    *(__nv_bfloat162*)dst       = __float22bfloat162_rn(make_float2(o[0], o[1]));
    *(__nv_bfloat162*)(dst + 2) = __float22bfloat162_rn(make_float2(o[2], o[3]));
}

// ---------------- launcher ----------------
extern "C" void kernel_launch(void* const* d_in, const int* in_sizes, int n_in,
                              void* d_out, int out_size)
{
    const float* u       = (const float*)d_in[0];
    const float* norm_w  = (const float*)d_in[1];
    const float* norm_b  = (const float*)d_in[2];
    const float* f_in_w  = (const float*)d_in[3];
    const float* f_cw    = (const float*)d_in[4];
    const float* f_cb    = (const float*)d_in[5];
    const float* f_Alog  = (const float*)d_in[6];
    const float* f_xpw   = (const float*)d_in[7];
    const float* f_dtw   = (const float*)d_in[8];
    const float* f_dtb   = (const float*)d_in[9];
    const float* f_D     = (const float*)d_in[10];
    const float* b_in_w  = (const float*)d_in[11];
    const float* b_cw    = (const float*)d_in[12];
    const float* b_cb    = (const float*)d_in[13];
    const float* b_Alog  = (const float*)d_in[14];
    const float* b_xpw   = (const float*)d_in[15];
    const float* b_dtw   = (const float*)d_in[16];
    const float* b_dtb   = (const float*)d_in[17];
    const float* b_D     = (const float*)d_in[18];
    const float* out_w   = (const float*)d_in[19];
    float* out = (float*)d_out;

    float *xdp, *odp;
    __nv_bfloat16 *un_bf, *xz_bf, *xc_bf, *xd_bf, *dt_bf, *ycat_bf;
    __nv_bfloat16 *inw_bf, *xpw_bf, *dtw_bf, *outw_bf;
    cudaGetSymbolAddress((void**)&xdp,    g_xdp);
    cudaGetSymbolAddress((void**)&odp,    g_odp);
    cudaGetSymbolAddress((void**)&un_bf,  g_un_bf);
    cudaGetSymbolAddress((void**)&xz_bf,  g_xz_bf);
    cudaGetSymbolAddress((void**)&xc_bf,  g_xc_bf);
    cudaGetSymbolAddress((void**)&xd_bf,  g_xd_bf);
    cudaGetSymbolAddress((void**)&dt_bf,  g_dt_bf);
    cudaGetSymbolAddress((void**)&ycat_bf,g_ycat_bf);
    cudaGetSymbolAddress((void**)&inw_bf, g_inw_bf);
    cudaGetSymbolAddress((void**)&xpw_bf, g_xpw_bf);
    cudaGetSymbolAddress((void**)&dtw_bf, g_dtw_bf);
    cudaGetSymbolAddress((void**)&outw_bf,g_outw_bf);

    __nv_bfloat16* xzb0 = xz_bf;  __nv_bfloat16* xzb1 = xz_bf + (size_t)TT*2*DI;
    __nv_bfloat16* xcb0 = xc_bf;  __nv_bfloat16* xcb1 = xc_bf + (size_t)TT*DI;
    __nv_bfloat16* xdb0 = xd_bf;  __nv_bfloat16* xdb1 = xd_bf + (size_t)TT*XDB;
    __nv_bfloat16* dtb0 = dt_bf;  __nv_bfloat16* dtb1 = dt_bf + (size_t)TT*DI;
    __nv_bfloat16* inw0 = inw_bf; __nv_bfloat16* inw1 = inw_bf + (size_t)IN_W;
    __nv_bfloat16* xpw0 = xpw_bf; __nv_bfloat16* xpw1 = xpw_bf + (size_t)XP_W;
    __nv_bfloat16* dtw0 = dtw_bf; __nv_bfloat16* dtw1 = dtw_bf + (size_t)DT_W;

    constexpr int SM_BIG = 3 * 32768;
    constexpr int SM_XP  = 4 * 192 * 64;
    constexpr int SM_DT  = 4 * 256 * 64;
    cudaFuncSetAttribute((const void*)gemm_big<0>,
        cudaFuncAttributeMaxDynamicSharedMemorySize, SM_BIG);
    cudaFuncSetAttribute((const void*)gemm_big<3>,
        cudaFuncAttributeMaxDynamicSharedMemorySize, SM_BIG);
    cudaFuncSetAttribute((const void*)gemm_xp,
        cudaFuncAttributeMaxDynamicSharedMemorySize, SM_XP);
    cudaFuncSetAttribute((const void*)gemm_dt,
        cudaFuncAttributeMaxDynamicSharedMemorySize, SM_DT);

    // 0) weights->bf16 + layernorm (merged)
    prep_kernel<<<NCVT + TT, 256>>>(u, norm_w, norm_b,
                                    f_in_w, b_in_w, f_xpw, b_xpw,
                                    f_dtw, b_dtw, out_w);

    // 1) in-proj -> bf16 xz
    gemm_big<0><<<dim3(2*DI/128, TT/128, 2), 128, SM_BIG>>>(
        un_bf, un_bf, DM, inw0, inw1, DM, nullptr, 2*DI, xzb0, xzb1, DM);

    // 2) conv + silu (bf16 in/out)
    conv_silu<<<dim3((TT/4)*(DI/4)/256, 2), 256>>>(f_cw, f_cb, b_cw, b_cb);

    // 3) xproj split-K x4 + reduce -> bf16 xd
    gemm_xp<<<dim3(1, TT/64, 2*XSPLIT), 128, SM_XP>>>(
        xcb0, xcb1, xpw0, xpw1, xdp);
    reduce_xd<<<dim3(TT*XDB/4/256, 2), 256>>>();

    // 4) dt: softplus+bias -> bf16
    gemm_dt<<<dim3(DI/128, TT/128, 2), 256, SM_DT>>>(
        xdb0, xdb1, dtw0, dtw1, dtb0, dtb1, f_dtb, b_dtb);

    // 5) selective scan (bf16 in) -> fp32 ycf
    scan_kernel<<<dim3(DI/8, Bb, 2), 128>>>(f_Alog, b_Alog, f_D, b_D);

    // 6) gate
    gate_kernel<<<dim3(TT*DI/4/256, 2), 256>>>();

    // 7) out-proj split-K x3 -> partials, then reduce + residual
    gemm_big<3><<<dim3(DM/128, TT/128, OSPLIT), 128, SM_BIG>>>(
        ycat_bf, nullptr, 2*DI, outw_bf, nullptr, 2*DI, odp, DM,
        nullptr, nullptr, (2*DI)/OSPLIT);
    reduce_out<<<TT*DM/4/256, 256>>>(u, out);
}

// round 17
// speedup vs baseline: 1.4115x; 1.0269x over previous
#include <cuda_runtime.h>
#include <cuda_bf16.h>
#include <math.h>
#include <stdint.h>

#define Bb   2
#define Lseq 1024
#define DM   768
#define DI   1536
#define NS   16
#define DTR  96
#define XDB  (DTR + 2*NS)   // 128
#define TT   (Bb*Lseq)      // 2048

#define IN_W  (2*DI*DM)
#define XP_W  (XDB*DI)
#define DT_W  (DI*DTR)
#define OUT_W (DM*2*DI)
#define WTOT  (2*IN_W + 2*XP_W + 2*DT_W + OUT_W)   // 7766016
#define NCVT  (WTOT/8/256)                          // 3792 blocks
#define OSPLIT 3
#define XSPLIT 4

// ---------------- fp32 scratch ----------------
__device__ float g_xdp[2*XSPLIT][TT*XDB];
__device__ float g_odp[OSPLIT][TT*DM];
__device__ float g_ycf[2][TT*DI];
// ---------------- bf16 scratch ----------------
__device__ __nv_bfloat16 g_un_bf[TT*DM];
__device__ __nv_bfloat16 g_xz_bf[2][TT*2*DI];
__device__ __nv_bfloat16 g_xc_bf[2][TT*DI];
__device__ __nv_bfloat16 g_xd_bf[2][TT*XDB];
__device__ __nv_bfloat16 g_dt_bf[2][TT*DI];
__device__ __nv_bfloat16 g_ycat_bf[TT*2*DI];
__device__ __nv_bfloat16 g_inw_bf[2][IN_W];
__device__ __nv_bfloat16 g_xpw_bf[2][XP_W];
__device__ __nv_bfloat16 g_dtw_bf[2][DT_W];
__device__ __nv_bfloat16 g_outw_bf[OUT_W];

// ---------------- helpers ----------------
__device__ __forceinline__ void cp16(uint32_t dst_s, const void* src) {
    asm volatile("cp.async.ca.shared.global [%0], [%1], 16;\n" :: "r"(dst_s), "l"(src));
}
__device__ __forceinline__ void cp_commit() {
    asm volatile("cp.async.commit_group;\n");
}
template<int N> __device__ __forceinline__ void cp_wait() {
    asm volatile("cp.async.wait_group %0;\n" :: "n"(N));
}
__device__ __forceinline__ void ldsm4(uint32_t& r0, uint32_t& r1,
                                      uint32_t& r2, uint32_t& r3, uint32_t a) {
    asm volatile("ldmatrix.sync.aligned.m8n8.x4.shared.b16 {%0,%1,%2,%3}, [%4];\n"
        : "=r"(r0), "=r"(r1), "=r"(r2), "=r"(r3) : "r"(a));
}
__device__ __forceinline__ void mma_bf16(
    float& c0, float& c1, float& c2, float& c3,
    uint32_t a0, uint32_t a1, uint32_t a2, uint32_t a3,
    uint32_t b0, uint32_t b1)
{
    asm volatile(
        "mma.sync.aligned.m16n8k16.row.col.f32.bf16.bf16.f32 "
        "{%0,%1,%2,%3}, {%4,%5,%6,%7}, {%8,%9}, {%0,%1,%2,%3};\n"
        : "+f"(c0), "+f"(c1), "+f"(c2), "+f"(c3)
        : "r"(a0), "r"(a1), "r"(a2), "r"(a3), "r"(b0), "r"(b1));
}
__device__ __forceinline__ uint32_t pk2(float a, float b) {
    __nv_bfloat162 h = __float22bfloat162_rn(make_float2(a, b));
    return *reinterpret_cast<uint32_t*>(&h);
}
__device__ __forceinline__ void ld4bf(const __nv_bfloat16* p, float* o) {
    uint2 r = *(const uint2*)p;
    __nv_bfloat162 lo = *reinterpret_cast<__nv_bfloat162*>(&r.x);
    __nv_bfloat162 hi = *reinterpret_cast<__nv_bfloat162*>(&r.y);
    float2 f0 = __bfloat1622float2(lo);
    float2 f1 = __bfloat1622float2(hi);
    o[0] = f0.x; o[1] = f0.y; o[2] = f1.x; o[3] = f1.y;
}

// ---------------- prep: weight cvt + layernorm ----------------
__global__ __launch_bounds__(256) void prep_kernel(
    const float* __restrict__ u, const float* __restrict__ nw,
    const float* __restrict__ nb,
    const float* __restrict__ fw, const float* __restrict__ bw,
    const float* __restrict__ fx, const float* __restrict__ bx,
    const float* __restrict__ fd, const float* __restrict__ bd,
    const float* __restrict__ ow)
{
    if (blockIdx.x < NCVT) {
        long long i = ((long long)blockIdx.x * 256 + threadIdx.x) * 8;
        const float* s; __nv_bfloat16* dst;
        if (i < IN_W)                 { s = fw + i; dst = &g_inw_bf[0][i]; }
        else if ((i -= IN_W) < IN_W)  { s = bw + i; dst = &g_inw_bf[1][i]; }
        else if ((i -= IN_W) < XP_W)  { s = fx + i; dst = &g_xpw_bf[0][i]; }
        else if ((i -= XP_W) < XP_W)  { s = bx + i; dst = &g_xpw_bf[1][i]; }
        else if ((i -= XP_W) < DT_W)  { s = fd + i; dst = &g_dtw_bf[0][i]; }
        else if ((i -= DT_W) < DT_W)  { s = bd + i; dst = &g_dtw_bf[1][i]; }
        else if ((i -= DT_W) < OUT_W) { s = ow + i; dst = &g_outw_bf[i]; }
        else return;
        float4 lo = *(const float4*)s;
        float4 hi = *(const float4*)(s + 4);
        uint4 o;
        o.x = pk2(lo.x, lo.y); o.y = pk2(lo.z, lo.w);
        o.z = pk2(hi.x, hi.y); o.w = pk2(hi.z, hi.w);
        *(uint4*)dst = o;
        return;
    }
    int t = blockIdx.x - NCVT;
    const float* row = u + (size_t)t * DM;
    float v[3];
    float s = 0.f, s2 = 0.f;
#pragma unroll
    for (int i = 0; i < 3; i++) {
        v[i] = row[threadIdx.x + i*256];
        s  += v[i];
        s2 += v[i]*v[i];
    }
#pragma unroll
    for (int o = 16; o; o >>= 1) {
        s  += __shfl_xor_sync(0xffffffffu, s,  o);
        s2 += __shfl_xor_sync(0xffffffffu, s2, o);
    }
    __shared__ float ss[8], ss2[8];
    int wid = threadIdx.x >> 5, ln = threadIdx.x & 31;
    if (ln == 0) { ss[wid] = s; ss2[wid] = s2; }
    __syncthreads();
    float ts = 0.f, ts2 = 0.f;
#pragma unroll
    for (int i = 0; i < 8; i++) { ts += ss[i]; ts2 += ss2[i]; }
    float mu  = ts * (1.f/DM);
    float var = ts2 * (1.f/DM) - mu*mu;
    float rs  = rsqrtf(var + 1e-5f);
#pragma unroll
    for (int i = 0; i < 3; i++) {
        int c = threadIdx.x + i*256;
        g_un_bf[(size_t)t*DM + c] = __float2bfloat16((v[i]-mu)*rs*nw[c] + nb[c]);
    }
}

// fragment-load macro (double-buffered) for gemm_big
#define LDFRAG_BIG(B, KK) do {                                                \
    _Pragma("unroll")                                                         \
    for (int ii = 0; ii < 4; ii++) {                                          \
        int row = wm*64 + ii*16 + arow;                                       \
        int pos = (2*(KK) + ach) ^ (row & 7);                                 \
        ldsm4(ar[B][ii][0], ar[B][ii][1], ar[B][ii][2], ar[B][ii][3],         \
              base + row*128 + pos*16);                                       \
    }                                                                         \
    _Pragma("unroll")                                                         \
    for (int j2 = 0; j2 < 4; j2++) {                                          \
        int row = wn*64 + j2*16 + brow;                                       \
        int pos = (2*(KK) + bch) ^ (row & 7);                                 \
        ldsm4(brr[B][2*j2][0], brr[B][2*j2][1],                               \
              brr[B][2*j2+1][0], brr[B][2*j2+1][1],                           \
              base + 16384 + row*128 + pos*16);                               \
    }                                                                         \
} while (0)

// ======== gemm_big: 128x128 CTA tile, 4 warps (64x64 each), k64 slabs ========
// 2-stage smem pipeline (64KB) -> 3 CTAs/SM.
// MODE 0: bf16 out (z = branch).  MODE 3: split-K fp32 partials (z = k-chunk).
template<int MODE>
__global__ void __launch_bounds__(128) gemm_big(
    const __nv_bfloat16* __restrict__ A0, const __nv_bfloat16* __restrict__ A1, int lda,
    const __nv_bfloat16* __restrict__ W0, const __nv_bfloat16* __restrict__ W1, int ldw,
    float* __restrict__ C0, int ldc,
    __nv_bfloat16* __restrict__ Cb0, __nv_bfloat16* __restrict__ Cb1,
    int K)
{
    extern __shared__ char smem[];
    uint32_t sb = (uint32_t)__cvta_generic_to_shared(smem);

    const __nv_bfloat16* A;
    const __nv_bfloat16* W;
    float* C = nullptr;
    __nv_bfloat16* Cb = nullptr;
    if (MODE == 3) {
        A = A0 + (size_t)blockIdx.z * K;
        W = W0 + (size_t)blockIdx.z * K;
        C = C0 + (size_t)blockIdx.z * ((size_t)TT * DM);
    } else {
        A  = blockIdx.z ? A1 : A0;
        W  = blockIdx.z ? W1 : W0;
        Cb = blockIdx.z ? Cb1 : Cb0;
    }

    int tid  = threadIdx.x;
    int lane = tid & 31;
    int w    = tid >> 5;
    int wm   = w >> 1;
    int wn   = w & 1;
    int bm   = blockIdx.y * 128;
    int bn   = blockIdx.x * 128;

    int ch = tid & 7;
    int rb = tid >> 3;
    const __nv_bfloat16* ap = A + (size_t)(bm + rb) * lda + ch * 8;
    const __nv_bfloat16* wp = W + (size_t)(bn + rb) * ldw + ch * 8;
    uint32_t ao = (uint32_t)(rb * 128 + ((ch ^ (rb & 7)) * 16));
    uint32_t bo = 16384u + ao;

    int nk = K / 64;
    // prime stage 0
    {
#pragma unroll
        for (int v = 0; v < 8; v++) {
            cp16(sb + ao + v*2048, ap + (size_t)v*16*lda);
            cp16(sb + bo + v*2048, wp + (size_t)v*16*ldw);
        }
        cp_commit();
    }

    float acc[4][8][4] = {};
    int arow = lane & 15;
    int ach  = lane >> 4;
    int brow = ((lane >> 4) << 3) + (lane & 7);
    int bch  = (lane >> 3) & 1;
    int r0   = lane >> 2;
    int c0   = lane & 3;

    uint32_t ar[2][4][4];
    uint32_t brr[2][8][2];

    for (int i = 0; i < nk; i++) {
        int st = i & 1;
        cp_wait<0>();          // stage i data complete
        __syncthreads();       // all warps done with stage i^1 (consumed at i-1)
        if (i + 1 < nk) {      // prefetch into stage i^1 (full-slab lead time)
            int s2 = st ^ 1;
#pragma unroll
            for (int v = 0; v < 8; v++) {
                cp16(sb + s2*32768 + ao + v*2048, ap + (size_t)v*16*lda + (i+1)*64);
                cp16(sb + s2*32768 + bo + v*2048, wp + (size_t)v*16*ldw + (i+1)*64);
            }
            cp_commit();
        }
        uint32_t base = sb + st*32768;
        LDFRAG_BIG(0, 0);
#pragma unroll
        for (int kk = 0; kk < 4; kk++) {
            int cur = kk & 1;
            if (kk == 0) LDFRAG_BIG(1, 1);
            else if (kk == 1) LDFRAG_BIG(0, 2);
            else if (kk == 2) LDFRAG_BIG(1, 3);
#pragma unroll
            for (int ii = 0; ii < 4; ii++)
#pragma unroll
                for (int j = 0; j < 8; j++)
                    mma_bf16(acc[ii][j][0], acc[ii][j][1],
                             acc[ii][j][2], acc[ii][j][3],
                             ar[cur][ii][0], ar[cur][ii][1],
                             ar[cur][ii][2], ar[cur][ii][3],
                             brr[cur][j][0], brr[cur][j][1]);
        }
    }

#pragma unroll
    for (int ii = 0; ii < 4; ii++) {
        int m0 = bm + wm*64 + ii*16 + r0;
#pragma unroll
        for (int j = 0; j < 8; j++) {
            int n0 = bn + wn*64 + j*8 + c0*2;
            if (MODE == 3) {
                *(float2*)&C[(size_t)m0 * ldc + n0] =
                    make_float2(acc[ii][j][0], acc[ii][j][1]);
                *(float2*)&C[(size_t)(m0+8) * ldc + n0] =
                    make_float2(acc[ii][j][2], acc[ii][j][3]);
            } else {
                *(uint32_t*)&Cb[(size_t)m0 * ldc + n0] =
                    pk2(acc[ii][j][0], acc[ii][j][1]);
                *(uint32_t*)&Cb[(size_t)(m0+8) * ldc + n0] =
                    pk2(acc[ii][j][2], acc[ii][j][3]);
            }
        }
    }
}

// ---------------- out-proj reduce ----------------
__global__ __launch_bounds__(256) void reduce_out(const float* __restrict__ u,
                                                  float* __restrict__ out)
{
    int i4 = (blockIdx.x * 256 + threadIdx.x) * 4;
    if (i4 >= TT*DM) return;
    float4 s = *(const float4*)&u[i4];
#pragma unroll
    for (int p = 0; p < OSPLIT; p++) {
        float4 a = *(const float4*)&g_odp[p][i4];
        s.x += a.x; s.y += a.y; s.z += a.z; s.w += a.w;
    }
    *(float4*)&out[i4] = s;
}

// frag loads for 32x64-warp-tile kernels (xp, dt)
#define LDFRAG_SM(B, KK) do {                                                 \
    _Pragma("unroll")                                                         \
    for (int ii = 0; ii < 2; ii++) {                                          \
        int row = wm*32 + ii*16 + arow;                                       \
        int pos = (2*(KK) + ach) ^ ((row >> 1) & 3);                          \
        ldsm4(ar[B][ii][0], ar[B][ii][1], ar[B][ii][2], ar[B][ii][3],         \
              stw + (row*16 + pos*4)*4);                                      \
    }                                                                         \
    _Pragma("unroll")                                                         \
    for (int j2 = 0; j2 < 4; j2++) {                                          \
        int row = wn*64 + j2*16 + brow;                                       \
        int pos = (2*(KK) + bch) ^ ((row >> 1) & 3);                          \
        ldsm4(brr[B][2*j2][0], brr[B][2*j2][1],                               \
              brr[B][2*j2+1][0], brr[B][2*j2+1][1],                           \
              stw + (BMv*16 + row*16 + pos*4)*4);                             \
    }                                                                         \
} while (0)

// ======== gemm_xp: xproj split-K x4.  BM=64, BN=128, 4 warps (32x64), K=384 ========
__global__ void __launch_bounds__(128) gemm_xp(
    const __nv_bfloat16* __restrict__ Ab0, const __nv_bfloat16* __restrict__ Ab1,
    const __nv_bfloat16* __restrict__ Wb0, const __nv_bfloat16* __restrict__ Wb1,
    float* __restrict__ Cp)
{
    constexpr int BMv = 64, THREADS = 128;
    constexpr int SWORDS = (BMv + 128) * 16;
    constexpr int LPT = (BMv + 128) * 4 / THREADS;  // 6
    constexpr int KPART = DI / XSPLIT;              // 384

    extern __shared__ uint32_t sm[];
    uint32_t smem_base = (uint32_t)__cvta_generic_to_shared(sm);

    int z  = blockIdx.z;
    int br = z >> 2;
    int kp = z & 3;
    const __nv_bfloat16* A = (br ? Ab1 : Ab0) + kp * KPART;
    const __nv_bfloat16* W = (br ? Wb1 : Wb0) + kp * KPART;
    float* C = Cp + (size_t)z * (TT*XDB);

    int tid  = threadIdx.x;
    int lane = tid & 31;
    int w    = tid >> 5;
    int wm   = w >> 1;
    int wn   = w & 1;
    int bm   = blockIdx.y * BMv;
    int r0   = lane >> 2;
    int c0   = lane & 3;

    const __nv_bfloat16* lsrc[LPT];
    uint32_t ldst[LPT];
#pragma unroll
    for (int u = 0; u < LPT; u++) {
        int i   = tid + u * THREADS;
        int row = i >> 2;
        int x   = i & 3;
        if (row < BMv) {
            lsrc[u] = A + (size_t)(bm + row) * DI + x * 8;
            ldst[u] = row * 16 + (x ^ ((row >> 1) & 3)) * 4;
        } else {
            int r = row - BMv;
            lsrc[u] = W + (size_t)r * DI + x * 8;
            ldst[u] = BMv * 16 + r * 16 + (x ^ ((r >> 1) & 3)) * 4;
        }
    }

    constexpr int nk = KPART / 32;   // 12
#pragma unroll
    for (int p = 0; p < 3; p++) {
#pragma unroll
        for (int u = 0; u < LPT; u++)
            cp16(smem_base + (p*SWORDS + ldst[u])*4, lsrc[u] + p*32);
        cp_commit();
    }

    float acc[2][8][4] = {};
    int arow = lane & 15;
    int ach  = lane >> 4;
    int brow = ((lane >> 4) << 3) + (lane & 7);
    int bch  = (lane >> 3) & 1;

    uint32_t ar[2][2][4];
    uint32_t brr[2][8][2];

    for (int i = 0; i < nk; i++) {
        int st = i & 3;
        int rem = nk - 1 - i;
        if (rem >= 2)      cp_wait<2>();
        else if (rem == 1) cp_wait<1>();
        else               cp_wait<0>();
        __syncthreads();
        if (i + 3 < nk) {
            int st2 = (i + 3) & 3;
#pragma unroll
            for (int u = 0; u < LPT; u++)
                cp16(smem_base + (st2*SWORDS + ldst[u])*4, lsrc[u] + (i+3)*32);
            cp_commit();
        }
        uint32_t stw = smem_base + st*SWORDS*4;
        LDFRAG_SM(0, 0);
#pragma unroll
        for (int kk = 0; kk < 2; kk++) {
            int cur = kk & 1;
            if (kk == 0) LDFRAG_SM(1, 1);
#pragma unroll
            for (int ii = 0; ii < 2; ii++)
#pragma unroll
                for (int j = 0; j < 8; j++)
                    mma_bf16(acc[ii][j][0], acc[ii][j][1],
                             acc[ii][j][2], acc[ii][j][3],
                             ar[cur][ii][0], ar[cur][ii][1],
                             ar[cur][ii][2], ar[cur][ii][3],
                             brr[cur][j][0], brr[cur][j][1]);
        }
    }

#pragma unroll
    for (int ii = 0; ii < 2; ii++) {
        int m0 = bm + wm*32 + ii*16 + r0;
#pragma unroll
        for (int j = 0; j < 8; j++) {
            int n0 = wn*64 + j*8 + c0*2;
            *(float2*)&C[(size_t)m0 * XDB + n0]     = make_float2(acc[ii][j][0], acc[ii][j][1]);
            *(float2*)&C[(size_t)(m0+8) * XDB + n0] = make_float2(acc[ii][j][2], acc[ii][j][3]);
        }
    }
}

// ---------------- reduce xproj partials -> bf16 ----------------
__global__ __launch_bounds__(256) void reduce_xd()
{
    int br = blockIdx.y;
    int i4 = (blockIdx.x * 256 + threadIdx.x) * 4;
    if (i4 >= TT*XDB) return;
    float4 s = *(const float4*)&g_xdp[br*XSPLIT][i4];
#pragma unroll
    for (int p = 1; p < XSPLIT; p++) {
        float4 a = *(const float4*)&g_xdp[br*XSPLIT + p][i4];
        s.x += a.x; s.y += a.y; s.z += a.z; s.w += a.w;
    }
    *(__nv_bfloat162*)&g_xd_bf[br][i4]   = __float22bfloat162_rn(make_float2(s.x, s.y));
    *(__nv_bfloat162*)&g_xd_bf[br][i4+2] = __float22bfloat162_rn(make_float2(s.z, s.w));
}

// ---------------- dt GEMM: 128x128, K=96, softplus, bf16 out ----------------
__global__ void __launch_bounds__(256) gemm_dt(
    const __nv_bfloat16* __restrict__ A0, const __nv_bfloat16* __restrict__ A1,
    const __nv_bfloat16* __restrict__ W0, const __nv_bfloat16* __restrict__ W1,
    __nv_bfloat16* __restrict__ C0, __nv_bfloat16* __restrict__ C1,
    const float* __restrict__ bias0, const float* __restrict__ bias1)
{
    constexpr int BMv = 128, THREADS = 256;
    constexpr int SWORDS = (BMv + 128) * 16;
    constexpr int LPT = (BMv + 128) * 4 / THREADS;  // 4
    constexpr int K = DTR;

    extern __shared__ uint32_t sm[];
    uint32_t smem_base = (uint32_t)__cvta_generic_to_shared(sm);

    const __nv_bfloat16* A = blockIdx.z ? A1 : A0;
    const __nv_bfloat16* W = blockIdx.z ? W1 : W0;
    __nv_bfloat16* C  = blockIdx.z ? C1 : C0;
    const float* bias = blockIdx.z ? bias1 : bias0;

    int tid  = threadIdx.x;
    int lane = tid & 31;
    int w    = tid >> 5;
    int wm   = w >> 1;
    int wn   = w & 1;
    int bm   = blockIdx.y * BMv;
    int bn   = blockIdx.x * 128;
    int r0   = lane >> 2;
    int c0   = lane & 3;

    const __nv_bfloat16* lsrc[LPT];
    uint32_t ldst[LPT];
#pragma unroll
    for (int u = 0; u < LPT; u++) {
        int i   = tid + u * THREADS;
        int row = i >> 2;
        int x   = i & 3;
        if (row < BMv) {
            lsrc[u] = A + (size_t)(bm + row) * XDB + x * 8;
            ldst[u] = row * 16 + (x ^ ((row >> 1) & 3)) * 4;
        } else {
            int r = row - BMv;
            lsrc[u] = W + (size_t)(bn + r) * DTR + x * 8;
            ldst[u] = BMv * 16 + r * 16 + (x ^ ((r >> 1) & 3)) * 4;
        }
    }

    constexpr int nk = K / 32;   // 3
#pragma unroll
    for (int p = 0; p < 3; p++) {
#pragma unroll
        for (int u = 0; u < LPT; u++)
            cp16(smem_base + (p*SWORDS + ldst[u])*4, lsrc[u] + p*32);
        cp_commit();
    }

    float acc[2][8][4] = {};
    int arow = lane & 15;
    int ach  = lane >> 4;
    int brow = ((lane >> 4) << 3) + (lane & 7);
    int bch  = (lane >> 3) & 1;

    uint32_t ar[2][2][4];
    uint32_t brr[2][8][2];

    for (int i = 0; i < nk; i++) {
        int st = i & 3;
        int rem = nk - 1 - i;
        if (rem >= 2)      cp_wait<2>();
        else if (rem == 1) cp_wait<1>();
        else               cp_wait<0>();
        __syncthreads();
        uint32_t stw = smem_base + st*SWORDS*4;
        LDFRAG_SM(0, 0);
#pragma unroll
        for (int kk = 0; kk < 2; kk++) {
            int cur = kk & 1;
            if (kk == 0) LDFRAG_SM(1, 1);
#pragma unroll
            for (int ii = 0; ii < 2; ii++)
#pragma unroll
                for (int j = 0; j < 8; j++)
                    mma_bf16(acc[ii][j][0], acc[ii][j][1],
                             acc[ii][j][2], acc[ii][j][3],
                             ar[cur][ii][0], ar[cur][ii][1],
                             ar[cur][ii][2], ar[cur][ii][3],
                             brr[cur][j][0], brr[cur][j][1]);
        }
    }

#pragma unroll
    for (int ii = 0; ii < 2; ii++) {
        int m0 = bm + wm*32 + ii*16 + r0;
#pragma unroll
        for (int j = 0; j < 8; j++) {
            int n0 = bn + wn*64 + j*8 + c0*2;
            float v0 = acc[ii][j][0], v1 = acc[ii][j][1];
            float v2 = acc[ii][j][2], v3 = acc[ii][j][3];
            float b0v = bias[n0], b1v = bias[n0 + 1];
            v0 += b0v; v1 += b1v; v2 += b0v; v3 += b1v;
            v0 = fmaxf(v0, 0.f) + log1pf(__expf(-fabsf(v0)));
            v1 = fmaxf(v1, 0.f) + log1pf(__expf(-fabsf(v1)));
            v2 = fmaxf(v2, 0.f) + log1pf(__expf(-fabsf(v2)));
            v3 = fmaxf(v3, 0.f) + log1pf(__expf(-fabsf(v3)));
            *(uint32_t*)&C[(size_t)m0 * DI + n0]     = pk2(v0, v1);
            *(uint32_t*)&C[(size_t)(m0+8) * DI + n0] = pk2(v2, v3);
        }
    }
}

// ------- conv (K=4) + silu; bf16 in/out; 4 tokens x 4 ch ------
__global__ __launch_bounds__(256) void conv_silu(
    const float* __restrict__ cw0, const float* __restrict__ cb0,
    const float* __restrict__ cw1, const float* __restrict__ cb1)
{
    int br = blockIdx.y;
    const float* cw = br ? cw1 : cw0;
    const float* cb = br ? cb1 : cb0;
    const __nv_bfloat16* xz = g_xz_bf[br];

    constexpr int ND4 = DI/4;
    int idx = blockIdx.x * 256 + threadIdx.x;
    if (idx >= (TT/4)*ND4) return;
    int tq = idx / ND4;
    int d4 = (idx % ND4) * 4;
    int t0 = tq * 4;
    int l0 = t0 % Lseq;

    float4 wr[4];
#pragma unroll
    for (int i = 0; i < 4; i++) wr[i] = *(const float4*)&cw[(d4+i)*4];
    float4 b4 = *(const float4*)&cb[d4];

    float X[7][4];
    if (br == 0) {
#pragma unroll
        for (int j = 0; j < 7; j++) {
            int off = j - 3;
            if (l0 + off >= 0) ld4bf(&xz[(size_t)(t0+off)*2*DI + d4], X[j]);
            else { X[j][0]=X[j][1]=X[j][2]=X[j][3]=0.f; }
        }
    } else {
#pragma unroll
        for (int j = 0; j < 7; j++) {
            if (l0 + j < Lseq) ld4bf(&xz[(size_t)(t0+j)*2*DI + d4], X[j]);
            else { X[j][0]=X[j][1]=X[j][2]=X[j][3]=0.f; }
        }
    }

    const float* Wp = (const float*)wr;
    const float* Bp = (const float*)&b4;
#pragma unroll
    for (int i2 = 0; i2 < 4; i2++) {
        float o[4];
#pragma unroll
        for (int c = 0; c < 4; c++) {
            float a = Bp[c];
            if (br == 0) {
                a = fmaf(Wp[c*4+0], X[i2][c],   a);
                a = fmaf(Wp[c*4+1], X[i2+1][c], a);
                a = fmaf(Wp[c*4+2], X[i2+2][c], a);
                a = fmaf(Wp[c*4+3], X[i2+3][c], a);
            } else {
                a = fmaf(Wp[c*4+3], X[i2][c],   a);
                a = fmaf(Wp[c*4+2], X[i2+1][c], a);
                a = fmaf(Wp[c*4+1], X[i2+2][c], a);
                a = fmaf(Wp[c*4+0], X[i2+3][c], a);
            }
            float sg = 1.f / (1.f + __expf(-a));
            o[c] = a * sg;
        }
        int t = t0 + i2;
        *(__nv_bfloat162*)&g_xc_bf[br][(size_t)t*DI + d4] =
            __float22bfloat162_rn(make_float2(o[0], o[1]));
        *(__nv_bfloat162*)&g_xc_bf[br][(size_t)t*DI + d4 + 2] =
            __float22bfloat162_rn(make_float2(o[2], o[3]));
    }
}

// ---------------- selective scan: bf16 in, 8-step pipelined, fp32 out ----------------
__global__ __launch_bounds__(128) void scan_kernel(
    const float* __restrict__ Alog0, const float* __restrict__ Alog1,
    const float* __restrict__ Dv0,   const float* __restrict__ Dv1)
{
    int br = blockIdx.z;
    int b  = blockIdx.y;
    const float* Alog = br ? Alog1 : Alog0;
    const float* Dvec = br ? Dv1   : Dv0;
    const __nv_bfloat16* dt = g_dt_bf[br];
    const __nv_bfloat16* xc = g_xc_bf[br];
    const __nv_bfloat16* xd = g_xd_bf[br];
    float* yo = g_ycf[br];

    int lane = threadIdx.x & 31;
    int warp = threadIdx.x >> 5;
    int n    = lane & 15;
    int d    = blockIdx.x * 8 + warp * 2 + (lane >> 4);

    float A  = -__expf(Alog[d*NS + n]);
    float Dp = Dvec[d];
    float h  = 0.f;

    int step = br ? -1 : 1;
    int t = b*Lseq + (br ? Lseq-1 : 0);

    float dt8[8], xv8[8], Bv8[8], Cv8[8];
    {
        int tq = t;
#pragma unroll
        for (int j = 0; j < 8; j++) {
            dt8[j] = __bfloat162float(dt[(size_t)tq*DI + d]);
            xv8[j] = __bfloat162float(xc[(size_t)tq*DI + d]);
            Bv8[j] = __bfloat162float(xd[(size_t)tq*XDB + DTR + n]);
            Cv8[j] = __bfloat162float(xd[(size_t)tq*XDB + DTR + NS + n]);
            tq += step;
        }
    }

    for (int s = 0; s < Lseq; s += 8) {
        float nd[8], nx[8], nB[8], nC[8];
        if (s + 8 < Lseq) {
            int tq = t + 8*step;
#pragma unroll
            for (int j = 0; j < 8; j++) {
                nd[j] = __bfloat162float(dt[(size_t)tq*DI + d]);
                nx[j] = __bfloat162float(xc[(size_t)tq*DI + d]);
                nB[j] = __bfloat162float(xd[(size_t)tq*XDB + DTR + n]);
                nC[j] = __bfloat162float(xd[(size_t)tq*XDB + DTR + NS + n]);
                tq += step;
            }
        } else {
#pragma unroll
            for (int j = 0; j < 8; j++) { nd[j]=0.f; nx[j]=0.f; nB[j]=0.f; nC[j]=0.f; }
        }
        float ya[8];
#pragma unroll
        for (int j = 0; j < 8; j++) {
            float a = __expf(dt8[j] * A);
            h = fmaf(a, h, dt8[j] * xv8[j] * Bv8[j]);
            ya[j] = h * Cv8[j];
        }
#pragma unroll
        for (int off = 8; off; off >>= 1) {
#pragma unroll
            for (int j = 0; j < 8; j++)
                ya[j] += __shfl_xor_sync(0xffffffffu, ya[j], off);
        }
        if (n == 0) {
#pragma unroll
            for (int j = 0; j < 8; j++) {
                int tj = t + j*step;
                yo[(size_t)tj*DI + d] = fmaf(xv8[j], Dp, ya[j]);
            }
        }
#pragma unroll
        for (int j = 0; j < 8; j++) {
            dt8[j] = nd[j]; xv8[j] = nx[j]; Bv8[j] = nB[j]; Cv8[j] = nC[j];
        }
        t += 8*step;
    }
}

// ---------------- gate: ycat_bf = ycf * silu(z) ----------------
__global__ __launch_bounds__(256) void gate_kernel()
{
    int br = blockIdx.y;
    int i4 = (blockIdx.x * 256 + threadIdx.x) * 4;
    if (i4 >= TT*DI) return;
    int t = i4 / DI;
    int d = i4 % DI;
    float4 y = *(const float4*)&g_ycf[br][i4];
    float zf[4];
    ld4bf(&g_xz_bf[br][(size_t)t*2*DI + DI + d], zf);
    float o[4];
    const float* yp = (const float*)&y;
#pragma unroll
    for (int i = 0; i < 4; i++) {
        float sz = zf[i] / (1.f + __expf(-zf[i]));
        o[i] = yp[i] * sz;
    }
    __nv_bfloat16* dst = &g_ycat_bf[(size_t)t*2*DI + br*DI + d];
    *(__nv_bfloat162*)dst       = __float22bfloat162_rn(make_float2(o[0], o[1]));
    *(__nv_bfloat162*)(dst + 2) = __float22bfloat162_rn(make_float2(o[2], o[3]));
}

// ---------------- launcher ----------------
extern "C" void kernel_launch(void* const* d_in, const int* in_sizes, int n_in,
                              void* d_out, int out_size)
{
    const float* u       = (const float*)d_in[0];
    const float* norm_w  = (const float*)d_in[1];
    const float* norm_b  = (const float*)d_in[2];
    const float* f_in_w  = (const float*)d_in[3];
    const float* f_cw    = (const float*)d_in[4];
    const float* f_cb    = (const float*)d_in[5];
    const float* f_Alog  = (const float*)d_in[6];
    const float* f_xpw   = (const float*)d_in[7];
    const float* f_dtw   = (const float*)d_in[8];
    const float* f_dtb   = (const float*)d_in[9];
    const float* f_D     = (const float*)d_in[10];
    const float* b_in_w  = (const float*)d_in[11];
    const float* b_cw    = (const float*)d_in[12];
    const float* b_cb    = (const float*)d_in[13];
    const float* b_Alog  = (const float*)d_in[14];
    const float* b_xpw   = (const float*)d_in[15];
    const float* b_dtw   = (const float*)d_in[16];
    const float* b_dtb   = (const float*)d_in[17];
    const float* b_D     = (const float*)d_in[18];
    const float* out_w   = (const float*)d_in[19];
    float* out = (float*)d_out;

    float *xdp, *odp;
    __nv_bfloat16 *un_bf, *xz_bf, *xc_bf, *xd_bf, *dt_bf, *ycat_bf;
    __nv_bfloat16 *inw_bf, *xpw_bf, *dtw_bf, *outw_bf;
    cudaGetSymbolAddress((void**)&xdp,    g_xdp);
    cudaGetSymbolAddress((void**)&odp,    g_odp);
    cudaGetSymbolAddress((void**)&un_bf,  g_un_bf);
    cudaGetSymbolAddress((void**)&xz_bf,  g_xz_bf);
    cudaGetSymbolAddress((void**)&xc_bf,  g_xc_bf);
    cudaGetSymbolAddress((void**)&xd_bf,  g_xd_bf);
    cudaGetSymbolAddress((void**)&dt_bf,  g_dt_bf);
    cudaGetSymbolAddress((void**)&ycat_bf,g_ycat_bf);
    cudaGetSymbolAddress((void**)&inw_bf, g_inw_bf);
    cudaGetSymbolAddress((void**)&xpw_bf, g_xpw_bf);
    cudaGetSymbolAddress((void**)&dtw_bf, g_dtw_bf);
    cudaGetSymbolAddress((void**)&outw_bf,g_outw_bf);

    __nv_bfloat16* xzb0 = xz_bf;  __nv_bfloat16* xzb1 = xz_bf + (size_t)TT*2*DI;
    __nv_bfloat16* xcb0 = xc_bf;  __nv_bfloat16* xcb1 = xc_bf + (size_t)TT*DI;
    __nv_bfloat16* xdb0 = xd_bf;  __nv_bfloat16* xdb1 = xd_bf + (size_t)TT*XDB;
    __nv_bfloat16* dtb0 = dt_bf;  __nv_bfloat16* dtb1 = dt_bf + (size_t)TT*DI;
    __nv_bfloat16* inw0 = inw_bf; __nv_bfloat16* inw1 = inw_bf + (size_t)IN_W;
    __nv_bfloat16* xpw0 = xpw_bf; __nv_bfloat16* xpw1 = xpw_bf + (size_t)XP_W;
    __nv_bfloat16* dtw0 = dtw_bf; __nv_bfloat16* dtw1 = dtw_bf + (size_t)DT_W;

    constexpr int SM_BIG = 2 * 32768;        // 65536 -> 3 CTAs/SM
    constexpr int SM_XP  = 4 * 192 * 64;
    constexpr int SM_DT  = 4 * 256 * 64;
    cudaFuncSetAttribute((const void*)gemm_big<0>,
        cudaFuncAttributeMaxDynamicSharedMemorySize, SM_BIG);
    cudaFuncSetAttribute((const void*)gemm_big<3>,
        cudaFuncAttributeMaxDynamicSharedMemorySize, SM_BIG);
    cudaFuncSetAttribute((const void*)gemm_xp,
        cudaFuncAttributeMaxDynamicSharedMemorySize, SM_XP);
    cudaFuncSetAttribute((const void*)gemm_dt,
        cudaFuncAttributeMaxDynamicSharedMemorySize, SM_DT);

    // 0) weights->bf16 + layernorm (merged)
    prep_kernel<<<NCVT + TT, 256>>>(u, norm_w, norm_b,
                                    f_in_w, b_in_w, f_xpw, b_xpw,
                                    f_dtw, b_dtw, out_w);

    // 1) in-proj -> bf16 xz
    gemm_big<0><<<dim3(2*DI/128, TT/128, 2), 128, SM_BIG>>>(
        un_bf, un_bf, DM, inw0, inw1, DM, nullptr, 2*DI, xzb0, xzb1, DM);

    // 2) conv + silu (bf16 in/out)
    conv_silu<<<dim3((TT/4)*(DI/4)/256, 2), 256>>>(f_cw, f_cb, b_cw, b_cb);

    // 3) xproj split-K x4 + reduce -> bf16 xd
    gemm_xp<<<dim3(1, TT/64, 2*XSPLIT), 128, SM_XP>>>(
        xcb0, xcb1, xpw0, xpw1, xdp);
    reduce_xd<<<dim3(TT*XDB/4/256, 2), 256>>>();

    // 4) dt: softplus+bias -> bf16
    gemm_dt<<<dim3(DI/128, TT/128, 2), 256, SM_DT>>>(
        xdb0, xdb1, dtw0, dtw1, dtb0, dtb1, f_dtb, b_dtb);

    // 5) selective scan (bf16 in) -> fp32 ycf
    scan_kernel<<<dim3(DI/8, Bb, 2), 128>>>(f_Alog, b_Alog, f_D, b_D);

    // 6) gate
    gate_kernel<<<dim3(TT*DI/4/256, 2), 256>>>();

    // 7) out-proj split-K x3 -> partials, then reduce + residual
    gemm_big<3><<<dim3(DM/128, TT/128, OSPLIT), 128, SM_BIG>>>(
        ycat_bf, nullptr, 2*DI, outw_bf, nullptr, 2*DI, odp, DM,
        nullptr, nullptr, (2*DI)/OSPLIT);
    reduce_out<<<TT*DM/4/256, 256>>>(u, out);
}